// round 7
// baseline (speedup 1.0000x reference)
#include <cuda_runtime.h>
#include <cuda_bf16.h>
#include <math.h>

// ---------------- problem constants ----------------
#define TT 64
#define BATCH 32
#define PE 128
#define WE 512
#define PH 256
#define WH 1024
#define PV 48
#define WV 32000

#define GRID 148
#define TPB  512

// ---------------- scratch ----------------
#define SZ_PEMB   (TT*BATCH*PE)
#define SZ_WEMB   (TT*BATCH*WE)
#define SZ_GPSEQ  (TT*BATCH*4*PH)
#define SZ_GWSEQ  (TT*BATCH*4*WH)
#define SZ_PH     (BATCH*PH)
#define SZ_WH     (BATCH*WH)
#define SZ_G4WH   (BATCH*4*WH)
#define SZ_PHSEQ  (TT*BATCH*PH)
#define SZ_WHSEQ  (TT*BATCH*WH)
#define SZ_HE     (TT*BATCH*WE)

#define OFF_PEMB   0
#define OFF_WEMB   (OFF_PEMB + SZ_PEMB)
#define OFF_GPSEQ  (OFF_WEMB + SZ_WEMB)
#define OFF_GWSEQ  (OFF_GPSEQ + SZ_GPSEQ)
#define OFF_PH0    (OFF_GWSEQ + SZ_GWSEQ)
#define OFF_PH1    (OFF_PH0 + SZ_PH)
#define OFF_PC     (OFF_PH1 + SZ_PH)
#define OFF_WH0A   (OFF_PC + SZ_PH)
#define OFF_WH0B   (OFF_WH0A + SZ_WH)
#define OFF_WC0    (OFF_WH0B + SZ_WH)
#define OFF_WH1A   (OFF_WC0 + SZ_WH)
#define OFF_WH1B   (OFF_WH1A + SZ_WH)
#define OFF_WC1    (OFF_WH1B + SZ_WH)
#define OFF_LASTW  (OFF_WC1 + SZ_WH)
#define OFF_LASTP  (OFF_LASTW + SZ_WH)
#define OFF_WG0H   (OFF_LASTP + SZ_PH)
#define OFF_WG1H   (OFF_WG0H + SZ_G4WH)
#define OFF_PHSEQ  (OFF_WG1H + SZ_G4WH)
#define OFF_WHSEQ  (OFF_PHSEQ + SZ_PHSEQ)
#define OFF_HE     (OFF_WHSEQ + SZ_WHSEQ)
#define SCRATCH_TOTAL (OFF_HE + SZ_HE)

__device__ float g_scratch[SCRATCH_TOTAL];
__device__ unsigned g_bar_cnt = 0;
__device__ unsigned g_bar_gen = 0;

// bf16 operands for the tensor-core vocab GEMM
__device__ __nv_bfloat16 g_wemb_bf[(size_t)WV * WE];
__device__ __nv_bfloat16 g_he_bf[(size_t)TT * BATCH * WE];

// dynamic smem for persist kernel: 32 rows x (1024/4+1) float4
#define SMEM_DYN (32 * 257 * 16)

__device__ __forceinline__ float sigf(float x) { return 1.f / (1.f + expf(-x)); }

// ---------------- init ----------------
__global__ void init_kernel(const int* __restrict__ pos, const int* __restrict__ word,
                            const float* __restrict__ pos_emb, const float* __restrict__ word_emb,
                            float* __restrict__ S)
{
    int i = blockIdx.x * blockDim.x + threadIdx.x;
    int stride = gridDim.x * blockDim.x;
    float* pemb = S + OFF_PEMB;
    float* wemb = S + OFF_WEMB;
    for (int idx = i; idx < TT*BATCH*PE; idx += stride) {
        int tb = idx / PE, e = idx - tb*PE;
        pemb[idx] = pos_emb[pos[tb]*PE + e];
    }
    for (int idx = i; idx < TT*BATCH*WE; idx += stride) {
        int tb = idx / WE, e = idx - tb*WE;
        wemb[idx] = word_emb[word[tb]*WE + e];
    }
    for (int idx = i; idx < 3*SZ_PH; idx += stride) S[OFF_PH0 + idx] = 0.f;
    for (int idx = i; idx < 6*SZ_WH; idx += stride) S[OFF_WH0A + idx] = 0.f;
}

// ---------------- fp32 -> bf16 conversion (vectorized) ----------------
__global__ void conv_bf16(const float* __restrict__ src, __nv_bfloat16* __restrict__ dst,
                          int n4)
{
    int i = blockIdx.x * blockDim.x + threadIdx.x;
    int st = gridDim.x * blockDim.x;
    const float4* s4 = (const float4*)src;
    for (; i < n4; i += st) {
        float4 v = s4[i];
        __nv_bfloat162 lo = __floats2bfloat162_rn(v.x, v.y);
        __nv_bfloat162 hi = __floats2bfloat162_rn(v.z, v.w);
        *(__nv_bfloat162*)(dst + (size_t)i*4)     = lo;
        *(__nv_bfloat162*)(dst + (size_t)i*4 + 2) = hi;
    }
}

// ---------------- grid barrier ----------------
__device__ __forceinline__ void grid_bar()
{
    __threadfence();
    __syncthreads();
    if (threadIdx.x == 0) {
        volatile unsigned* gen = &g_bar_gen;
        unsigned g = *gen;
        unsigned a = atomicAdd(&g_bar_cnt, 1u);
        if (a == GRID - 1u) {
            g_bar_cnt = 0u;
            __threadfence();
            atomicAdd(&g_bar_gen, 1u);
        } else {
            while (*gen == g) __nanosleep(32);
        }
    }
    __syncthreads();
    __threadfence();
}

// ---------------- A staging into padded smem ----------------
__device__ __forceinline__ void stage_if(const float* A, int K, float* sAdyn,
                                         const float* volatile* s_staged)
{
    if (*s_staged != A) {
        __syncthreads();
        int K4 = K >> 2;
        const float4* A4 = (const float4*)A;
        float4* S4 = (float4*)sAdyn;
        for (int i = threadIdx.x; i < 32*K4; i += TPB) {
            int row = i / K4, kq = i - row*K4;
            S4[row*(K4+1) + kq] = A4[row*K4 + kq];
        }
        if (threadIdx.x == 0) *s_staged = A;
        __syncthreads();
    }
}

// ---------------- per-warp 4-col K-slice accumulate (software-pipelined) ----------------
__device__ __forceinline__ float fma4f(float acc, float4 a, float4 b)
{
    return fmaf(a.x, b.x, fmaf(a.y, b.y, fmaf(a.z, b.z, fmaf(a.w, b.w, acc))));
}

__device__ __forceinline__ void accum4(const float* __restrict__ W, int ldw, int wcol, int K,
                                       const int* n, int s, float* acc,
                                       const float* __restrict__ sAdyn)
{
    int lane = threadIdx.x & 31;
    int K4 = K >> 2;
    int Q  = K4 >> 2;                       // float4 groups per slice (>=16, even)
    const float4* a4 = (const float4*)sAdyn + lane*(K4+1);
    const float4* W0 = (const float4*)(W + (size_t)n[0]*ldw + wcol);
    const float4* W1 = (const float4*)(W + (size_t)n[1]*ldw + wcol);
    const float4* W2 = (const float4*)(W + (size_t)n[2]*ldw + wcol);
    const float4* W3 = (const float4*)(W + (size_t)n[3]*ldw + wcol);
    int q0 = s*Q, q1 = q0 + Q;
    float acc2[4] = {0.f, 0.f, 0.f, 0.f};
    #pragma unroll 4
    for (int q = q0; q < q1; q += 2) {
        // batch all 8 W loads (warp-uniform L2 hits) before any FMA -> high MLP
        float4 u0 = __ldg(W0+q),   u1 = __ldg(W1+q),   u2 = __ldg(W2+q),   u3 = __ldg(W3+q);
        float4 v0 = __ldg(W0+q+1), v1 = __ldg(W1+q+1), v2 = __ldg(W2+q+1), v3 = __ldg(W3+q+1);
        float4 a0 = a4[q], a1 = a4[q+1];
        acc[0]  = fma4f(acc[0],  a0, u0);
        acc[1]  = fma4f(acc[1],  a0, u1);
        acc[2]  = fma4f(acc[2],  a0, u2);
        acc[3]  = fma4f(acc[3],  a0, u3);
        acc2[0] = fma4f(acc2[0], a1, v0);
        acc2[1] = fma4f(acc2[1], a1, v1);
        acc2[2] = fma4f(acc2[2], a1, v2);
        acc2[3] = fma4f(acc2[3], a1, v3);
    }
    #pragma unroll
    for (int c = 0; c < 4; c++) acc[c] += acc2[c];
}

// ---------------- persistent sequential-phase kernel ----------------
__global__ __launch_bounds__(TPB, 1) void persist_kernel(
    const float* __restrict__ w2p_W, const float* __restrict__ w2p_b,
    const float* __restrict__ p2w_W, const float* __restrict__ p2w_b,
    const float* __restrict__ p_Wih0, const float* __restrict__ p_Whh0,
    const float* __restrict__ w_Wih0, const float* __restrict__ w_Whh0,
    const float* __restrict__ w_Wih1, const float* __restrict__ w_Whh1,
    const float* __restrict__ w_bih1, const float* __restrict__ w_bhh1,
    float* __restrict__ S)
{
    extern __shared__ float sA[];
    __shared__ float red[4][16][33];
    __shared__ const float* volatile s_staged;

    float* gpseq = S + OFF_GPSEQ;
    float* gwseq = S + OFF_GWSEQ;
    float* phb[2]  = { S + OFF_PH0,  S + OFF_PH1 };
    float* pc    = S + OFF_PC;
    float* wh0b[2] = { S + OFF_WH0A, S + OFF_WH0B };
    float* wc0   = S + OFF_WC0;
    float* wh1b[2] = { S + OFF_WH1A, S + OFF_WH1B };
    float* wc1   = S + OFF_WC1;
    float* lastw = S + OFF_LASTW;
    float* lastp = S + OFF_LASTP;
    float* wg0h  = S + OFF_WG0H;
    float* wg1h  = S + OFF_WG1H;
    float* phseq = S + OFF_PHSEQ;
    float* whseq = S + OFF_WHSEQ;

    int lane = threadIdx.x & 31;
    int wrp  = threadIdx.x >> 5;
    int s    = wrp & 3;
    int cg   = wrp >> 2;

    if (threadIdx.x == 0) s_staged = nullptr;
    __syncthreads();

    int pp = 0, pw0 = 0, pw1 = 0;

    for (int t = 0; t < TT; t++) {
        const float* wh1c = wh1b[pw1];
        const float* wh0c = wh0b[pw0];

        // ===== S1: lastw (tanh), wg1h, wg0h =====
        for (int gid = blockIdx.x; gid < 576; gid += GRID) {
            const float* A; const float* W; float* dst; const float* bias;
            int n0, Ntot, epi;
            if (gid < 64)       { A=wh1c; W=w2p_W;  dst=lastw; bias=w2p_b; n0=gid*16;        Ntot=WH;   epi=1; }
            else if (gid < 320) { A=wh1c; W=w_Whh1; dst=wg1h;  bias=0;     n0=(gid-64)*16;   Ntot=4*WH; epi=0; }
            else                { A=wh0c; W=w_Whh0; dst=wg0h;  bias=0;     n0=(gid-320)*16;  Ntot=4*WH; epi=0; }
            stage_if(A, WH, sA, &s_staged);
            int n[4]; float acc[4] = {0,0,0,0};
            #pragma unroll
            for (int c = 0; c < 4; c++) n[c] = n0 + cg*4 + c;
            accum4(W, WH, 0, WH, n, s, acc, sA);
            #pragma unroll
            for (int c = 0; c < 4; c++) red[s][cg*4+c][lane] = acc[c];
            __syncthreads();
            {
                float v = red[0][wrp][lane] + red[1][wrp][lane]
                        + red[2][wrp][lane] + red[3][wrp][lane];
                int nn = n0 + wrp;
                if (epi) dst[lane*Ntot + nn] = tanhf(v + bias[nn]);
                else     dst[lane*Ntot + nn] = v;
            }
            __syncthreads();
        }
        grid_bar();
        if (threadIdx.x == 0) s_staged = nullptr;
        __syncthreads();

        // ===== S2: POS gates + cell =====
        const float* phc = phb[pp];
        float* phn = phb[pp^1];
        for (int gid = blockIdx.x; gid < 64; gid += GRID) {
            int j0 = gid*4;
            int n[4]; float acc[4] = {0,0,0,0};
            #pragma unroll
            for (int c = 0; c < 4; c++) n[c] = cg*PH + j0 + c;
            stage_if(lastw, WH, sA, &s_staged);
            accum4(p_Wih0, PE+WH, PE, WH, n, s, acc, sA);
            stage_if(phc, PH, sA, &s_staged);
            accum4(p_Whh0, PH, 0, PH, n, s, acc, sA);
            #pragma unroll
            for (int c = 0; c < 4; c++) red[s][cg*4+c][lane] = acc[c];
            __syncthreads();
            if (threadIdx.x < 128) {
                int jl = wrp, b = lane;
                int j = j0 + jl;
                const float* pre = gpseq + ((size_t)t*BATCH + b)*4*PH;
                float g[4];
                #pragma unroll
                for (int gate = 0; gate < 4; gate++) {
                    int cc = gate*4 + jl;
                    g[gate] = red[0][cc][b] + red[1][cc][b] + red[2][cc][b] + red[3][cc][b]
                            + pre[gate*PH + j];
                }
                float si = sigf(g[0]), sf = sigf(g[1]), so = sigf(g[3]);
                int idx = b*PH + j;
                float cn = sf * pc[idx] + si * tanhf(g[2]);
                float hn = so * tanhf(cn);
                pc[idx] = cn; phn[idx] = hn;
                phseq[((size_t)t*BATCH + b)*PH + j] = hn;
            }
            __syncthreads();
        }
        grid_bar();
        if (threadIdx.x == 0) s_staged = nullptr;
        __syncthreads();

        // ===== S3: lastp = tanh(phn @ p2w^T + b) =====
        for (int gid = blockIdx.x; gid < 16; gid += GRID) {
            int n0 = gid*16;
            int n[4]; float acc[4] = {0,0,0,0};
            #pragma unroll
            for (int c = 0; c < 4; c++) n[c] = n0 + cg*4 + c;
            stage_if(phn, PH, sA, &s_staged);
            accum4(p2w_W, PH, 0, PH, n, s, acc, sA);
            #pragma unroll
            for (int c = 0; c < 4; c++) red[s][cg*4+c][lane] = acc[c];
            __syncthreads();
            {
                float v = red[0][wrp][lane] + red[1][wrp][lane]
                        + red[2][wrp][lane] + red[3][wrp][lane];
                int nn = n0 + wrp;
                lastp[lane*PH + nn] = tanhf(v + p2w_b[nn]);
            }
            __syncthreads();
        }
        grid_bar();
        if (threadIdx.x == 0) s_staged = nullptr;
        __syncthreads();

        // ===== S4: WORD L0 gates + cell =====
        float* wh0n = wh0b[pw0^1];
        for (int gid = blockIdx.x; gid < 256; gid += GRID) {
            int j0 = gid*4;
            int n[4]; float acc[4] = {0,0,0,0};
            #pragma unroll
            for (int c = 0; c < 4; c++) n[c] = cg*WH + j0 + c;
            stage_if(lastp, PH, sA, &s_staged);
            accum4(w_Wih0, WE+PH, WE, PH, n, s, acc, sA);
            #pragma unroll
            for (int c = 0; c < 4; c++) red[s][cg*4+c][lane] = acc[c];
            __syncthreads();
            if (threadIdx.x < 128) {
                int jl = wrp, b = lane;
                int j = j0 + jl;
                const float* pre = gwseq + ((size_t)t*BATCH + b)*4*WH;
                const float* hid = wg0h + (size_t)b*4*WH;
                float g[4];
                #pragma unroll
                for (int gate = 0; gate < 4; gate++) {
                    int cc = gate*4 + jl;
                    int nn = gate*WH + j;
                    g[gate] = red[0][cc][b] + red[1][cc][b] + red[2][cc][b] + red[3][cc][b]
                            + pre[nn] + hid[nn];
                }
                float si = sigf(g[0]), sf = sigf(g[1]), so = sigf(g[3]);
                int idx = b*WH + j;
                float cn = sf * wc0[idx] + si * tanhf(g[2]);
                float hn = so * tanhf(cn);
                wc0[idx] = cn; wh0n[idx] = hn;
            }
            __syncthreads();
        }
        grid_bar();
        if (threadIdx.x == 0) s_staged = nullptr;
        __syncthreads();
        pw0 ^= 1;

        // ===== S5: WORD L1 gates + cell =====
        float* wh1n = wh1b[pw1^1];
        const float* wh0new = wh0b[pw0];
        for (int gid = blockIdx.x; gid < 256; gid += GRID) {
            int j0 = gid*4;
            int n[4]; float acc[4] = {0,0,0,0};
            #pragma unroll
            for (int c = 0; c < 4; c++) n[c] = cg*WH + j0 + c;
            stage_if(wh0new, WH, sA, &s_staged);
            accum4(w_Wih1, WH, 0, WH, n, s, acc, sA);
            #pragma unroll
            for (int c = 0; c < 4; c++) red[s][cg*4+c][lane] = acc[c];
            __syncthreads();
            if (threadIdx.x < 128) {
                int jl = wrp, b = lane;
                int j = j0 + jl;
                const float* hid = wg1h + (size_t)b*4*WH;
                float g[4];
                #pragma unroll
                for (int gate = 0; gate < 4; gate++) {
                    int cc = gate*4 + jl;
                    int nn = gate*WH + j;
                    g[gate] = red[0][cc][b] + red[1][cc][b] + red[2][cc][b] + red[3][cc][b]
                            + hid[nn] + w_bih1[nn] + w_bhh1[nn];
                }
                float si = sigf(g[0]), sf = sigf(g[1]), so = sigf(g[3]);
                int idx = b*WH + j;
                float cn = sf * wc1[idx] + si * tanhf(g[2]);
                float hn = so * tanhf(cn);
                wc1[idx] = cn; wh1n[idx] = hn;
                whseq[((size_t)t*BATCH + b)*WH + j] = hn;
            }
            __syncthreads();
        }
        grid_bar();
        if (threadIdx.x == 0) s_staged = nullptr;
        __syncthreads();
        pw1 ^= 1;
        pp  ^= 1;
    }
}

// ---------------- big GEMM (fp32): C[M,N] = A[M,K] @ W[N, wcol:wcol+K]^T + b1 (+b2) ----------------
__global__ __launch_bounds__(256) void big_gemm(const float* __restrict__ A, int lda,
                                                const float* __restrict__ W, int ldw, int wcol,
                                                const float* __restrict__ bias1,
                                                const float* __restrict__ bias2,
                                                float* __restrict__ C, long ldc, int K)
{
    __shared__ float sAa[16][132];
    __shared__ float sW[16][68];
    int tx = threadIdx.x & 15, ty = threadIdx.x >> 4;
    int bm = blockIdx.y * 128, bn = blockIdx.x * 64;
    float acc[8][4];
    #pragma unroll
    for (int i = 0; i < 8; i++)
        #pragma unroll
        for (int j = 0; j < 4; j++) acc[i][j] = 0.f;

    for (int kt = 0; kt < K; kt += 16) {
        __syncthreads();
        #pragma unroll
        for (int i = 0; i < 2; i++) {
            int f = threadIdx.x + i*256;
            int row = f >> 2, kq = (f & 3) * 4;
            float4 v = *reinterpret_cast<const float4*>(A + (long)(bm+row)*lda + kt + kq);
            sAa[kq][row] = v.x; sAa[kq+1][row] = v.y; sAa[kq+2][row] = v.z; sAa[kq+3][row] = v.w;
        }
        {
            int f = threadIdx.x;
            int row = f >> 2, kq = (f & 3) * 4;
            float4 v = *reinterpret_cast<const float4*>(W + (long)(bn+row)*ldw + wcol + kt + kq);
            sW[kq][row] = v.x; sW[kq+1][row] = v.y; sW[kq+2][row] = v.z; sW[kq+3][row] = v.w;
        }
        __syncthreads();
        #pragma unroll
        for (int k = 0; k < 16; k++) {
            float4 a0 = *reinterpret_cast<float4*>(&sAa[k][ty*8]);
            float4 a1 = *reinterpret_cast<float4*>(&sAa[k][ty*8+4]);
            float4 w  = *reinterpret_cast<float4*>(&sW[k][tx*4]);
            float am[8] = {a0.x,a0.y,a0.z,a0.w,a1.x,a1.y,a1.z,a1.w};
            float wn[4] = {w.x,w.y,w.z,w.w};
            #pragma unroll
            for (int i = 0; i < 8; i++)
                #pragma unroll
                for (int j = 0; j < 4; j++)
                    acc[i][j] = fmaf(am[i], wn[j], acc[i][j]);
        }
    }

    float bv[4];
    #pragma unroll
    for (int j = 0; j < 4; j++) {
        int nn = bn + tx*4 + j;
        bv[j] = (bias1 ? bias1[nn] : 0.f) + (bias2 ? bias2[nn] : 0.f);
    }
    #pragma unroll
    for (int i = 0; i < 8; i++) {
        int m = bm + ty*8 + i;
        float4 o;
        o.x = acc[i][0] + bv[0]; o.y = acc[i][1] + bv[1];
        o.z = acc[i][2] + bv[2]; o.w = acc[i][3] + bv[3];
        *reinterpret_cast<float4*>(C + (long)m*ldc + bn + tx*4) = o;
    }
}

// ---------------- tensor-core vocab GEMM ----------------
__device__ __forceinline__ void mma16816(float* c, const unsigned* a, const unsigned* b)
{
    asm volatile("mma.sync.aligned.m16n8k16.row.col.f32.bf16.bf16.f32 "
        "{%0,%1,%2,%3}, {%4,%5,%6,%7}, {%8,%9}, {%0,%1,%2,%3};"
        : "+f"(c[0]), "+f"(c[1]), "+f"(c[2]), "+f"(c[3])
        : "r"(a[0]), "r"(a[1]), "r"(a[2]), "r"(a[3]), "r"(b[0]), "r"(b[1]));
}

__device__ __forceinline__ void ldsm4(unsigned* r, const void* p)
{
    unsigned ad = (unsigned)__cvta_generic_to_shared(p);
    asm volatile("ldmatrix.sync.aligned.m8n8.x4.shared.b16 {%0,%1,%2,%3}, [%4];"
        : "=r"(r[0]), "=r"(r[1]), "=r"(r[2]), "=r"(r[3]) : "r"(ad));
}

__global__ __launch_bounds__(256) void vocab_mma(const __nv_bfloat16* __restrict__ Abf,
                                                 const __nv_bfloat16* __restrict__ Bbf,
                                                 const float* __restrict__ bias,
                                                 float* __restrict__ C)
{
    __shared__ __nv_bfloat16 sAm[128][40];
    __shared__ __nv_bfloat16 sBm[128][40];
    int tid = threadIdx.x;
    int lane = tid & 31, wid = tid >> 5;
    int wm = wid >> 2, wn = wid & 3;
    int bm = blockIdx.y * 128, bn = blockIdx.x * 128;

    float acc[4][4][4] = {};

    for (int kt = 0; kt < WE; kt += 32) {
        __syncthreads();
        #pragma unroll
        for (int c = 0; c < 2; c++) {
            int ch = tid + c*256;
            int row = ch >> 2, seg = (ch & 3) * 8;
            *(uint4*)&sAm[row][seg] = *(const uint4*)&Abf[(size_t)(bm+row)*WE + kt + seg];
            *(uint4*)&sBm[row][seg] = *(const uint4*)&Bbf[(size_t)(bn+row)*WE + kt + seg];
        }
        __syncthreads();
        #pragma unroll
        for (int k16 = 0; k16 < 2; k16++) {
            unsigned afrag[4][4], bfrag[4][2];
            #pragma unroll
            for (int mf = 0; mf < 4; mf++) {
                int row = wm*64 + mf*16 + (lane & 15);
                int col = k16*16 + (lane >> 4) * 8;
                ldsm4(afrag[mf], &sAm[row][col]);
            }
            #pragma unroll
            for (int np = 0; np < 2; np++) {
                int row = wn*32 + np*16 + (lane & 7) + ((lane >> 4) << 3);
                int col = k16*16 + (((lane >> 3) & 1) << 3);
                unsigned r[4];
                ldsm4(r, &sBm[row][col]);
                bfrag[np*2][0]   = r[0]; bfrag[np*2][1]   = r[1];
                bfrag[np*2+1][0] = r[2]; bfrag[np*2+1][1] = r[3];
            }
            #pragma unroll
            for (int mf = 0; mf < 4; mf++)
                #pragma unroll
                for (int nf = 0; nf < 4; nf++)
                    mma16816(acc[mf][nf], afrag[mf], bfrag[nf]);
        }
    }

    int tg = lane >> 2;
    int tc = (lane & 3) * 2;
    #pragma unroll
    for (int nf = 0; nf < 4; nf++) {
        int n = bn + wn*32 + nf*8 + tc;
        float b0 = bias[n], b1 = bias[n+1];
        #pragma unroll
        for (int mf = 0; mf < 4; mf++) {
            int m0 = bm + wm*64 + mf*16 + tg;
            float2 v0 = { acc[mf][nf][0] + b0, acc[mf][nf][1] + b1 };
            float2 v1 = { acc[mf][nf][2] + b0, acc[mf][nf][3] + b1 };
            *(float2*)&C[(size_t)m0*WV + n]     = v0;
            *(float2*)&C[(size_t)(m0+8)*WV + n] = v1;
        }
    }
}

// ---------------- pos projection + log_softmax (48-way) ----------------
__global__ void pos_out_kernel(const float* __restrict__ phseq,
                               const float* __restrict__ proj_W,
                               const float* __restrict__ proj_b,
                               float* __restrict__ out)
{
    int row = blockIdx.x;
    const float* h = phseq + row * PH;
    __shared__ float sh[PH];
    __shared__ float logits[PV];
    __shared__ float lse;
    for (int i = threadIdx.x; i < PH; i += 64) sh[i] = h[i];
    __syncthreads();
    if (threadIdx.x < PV) {
        float s = proj_b[threadIdx.x];
        const float* wr = proj_W + threadIdx.x * PH;
        #pragma unroll 4
        for (int k = 0; k < PH; k++) s += sh[k] * wr[k];
        logits[threadIdx.x] = s;
    }
    __syncthreads();
    if (threadIdx.x == 0) {
        float m = -1e30f;
        for (int i = 0; i < PV; i++) m = fmaxf(m, logits[i]);
        float ssum = 0.f;
        for (int i = 0; i < PV; i++) ssum += expf(logits[i] - m);
        lse = m + logf(ssum);
    }
    __syncthreads();
    if (threadIdx.x < PV) out[row * PV + threadIdx.x] = logits[threadIdx.x] - lse;
}

// ---------------- in-place log_softmax over rows of WV ----------------
__global__ void word_lsm(float* __restrict__ out)
{
    int row = blockIdx.x;
    float* r = out + (long)row * WV;
    float m = -1e30f, s = 0.f;
    for (int i = threadIdx.x; i < WV; i += blockDim.x) {
        float v = r[i];
        if (v > m) { s = s * expf(m - v) + 1.f; m = v; }
        else       { s += expf(v - m); }
    }
    __shared__ float sm[256], ss[256];
    sm[threadIdx.x] = m; ss[threadIdx.x] = s;
    __syncthreads();
    for (int off = 128; off > 0; off >>= 1) {
        if (threadIdx.x < off) {
            float m1 = sm[threadIdx.x], s1 = ss[threadIdx.x];
            float m2 = sm[threadIdx.x + off], s2 = ss[threadIdx.x + off];
            float mm = fmaxf(m1, m2);
            sm[threadIdx.x] = mm;
            ss[threadIdx.x] = s1 * expf(m1 - mm) + s2 * expf(m2 - mm);
        }
        __syncthreads();
    }
    float lse = sm[0] + logf(ss[0]);
    for (int i = threadIdx.x; i < WV; i += blockDim.x) r[i] -= lse;
}

// ---------------- host orchestration ----------------
extern "C" void kernel_launch(void* const* d_in, const int* in_sizes, int n_in,
                              void* d_out, int out_size)
{
    (void)in_sizes; (void)n_in; (void)out_size;
    const int*   pos          = (const int*)  d_in[0];
    const int*   word         = (const int*)  d_in[1];
    const float* pos_emb_W    = (const float*)d_in[2];
    const float* word_emb_W   = (const float*)d_in[3];
    const float* w2p_W        = (const float*)d_in[4];
    const float* w2p_b        = (const float*)d_in[5];
    const float* p2w_W        = (const float*)d_in[6];
    const float* p2w_b        = (const float*)d_in[7];
    const float* p_Wih0       = (const float*)d_in[8];
    const float* p_Whh0       = (const float*)d_in[9];
    const float* p_bih0       = (const float*)d_in[10];
    const float* p_bhh0       = (const float*)d_in[11];
    const float* w_Wih0       = (const float*)d_in[12];
    const float* w_Whh0       = (const float*)d_in[13];
    const float* w_bih0       = (const float*)d_in[14];
    const float* w_bhh0       = (const float*)d_in[15];
    const float* w_Wih1       = (const float*)d_in[16];
    const float* w_Whh1       = (const float*)d_in[17];
    const float* w_bih1       = (const float*)d_in[18];
    const float* w_bhh1       = (const float*)d_in[19];
    const float* pos_proj_W   = (const float*)d_in[20];
    const float* pos_proj_b   = (const float*)d_in[21];
    const float* word_proj1_W = (const float*)d_in[22];
    const float* word_proj1_b = (const float*)d_in[23];
    const float* word_proj2_b = (const float*)d_in[24];
    float* out = (float*)d_out;

    float* S = nullptr;
    cudaGetSymbolAddress((void**)&S, g_scratch);
    __nv_bfloat16* wemb_bf = nullptr;
    cudaGetSymbolAddress((void**)&wemb_bf, g_wemb_bf);
    __nv_bfloat16* he_bf = nullptr;
    cudaGetSymbolAddress((void**)&he_bf, g_he_bf);

    float* pemb  = S + OFF_PEMB;
    float* wemb  = S + OFF_WEMB;
    float* gpseq = S + OFF_GPSEQ;
    float* gwseq = S + OFF_GWSEQ;
    float* phseq = S + OFF_PHSEQ;
    float* whseq = S + OFF_WHSEQ;
    float* he    = S + OFF_HE;

    static bool attr_set = false;
    if (!attr_set) {
        cudaFuncSetAttribute(persist_kernel, cudaFuncAttributeMaxDynamicSharedMemorySize, SMEM_DYN);
        attr_set = true;
    }

    init_kernel<<<256, 256>>>(pos, word, pos_emb_W, word_emb_W, S);

    conv_bf16<<<2048, 256>>>(word_emb_W, wemb_bf, (int)((size_t)WV*WE/4));

    big_gemm<<<dim3(4*PH/64, TT*BATCH/128), 256>>>(pemb, PE, p_Wih0, PE+WH, 0,
                                                   p_bih0, p_bhh0, gpseq, 4*PH, PE);
    big_gemm<<<dim3(4*WH/64, TT*BATCH/128), 256>>>(wemb, WE, w_Wih0, WE+PH, 0,
                                                   w_bih0, w_bhh0, gwseq, 4*WH, WE);

    persist_kernel<<<GRID, TPB, SMEM_DYN>>>(
        w2p_W, w2p_b, p2w_W, p2w_b,
        p_Wih0, p_Whh0, w_Wih0, w_Whh0,
        w_Wih1, w_Whh1, w_bih1, w_bhh1, S);

    pos_out_kernel<<<TT*BATCH, 64>>>(phseq, pos_proj_W, pos_proj_b, out);

    big_gemm<<<dim3(WE/64, TT*BATCH/128), 256>>>(whseq, WH, word_proj1_W, WH, 0,
                                                 word_proj1_b, nullptr, he, WE, WH);
    conv_bf16<<<1024, 256>>>(he, he_bf, (int)((size_t)TT*BATCH*WE/4));

    float* wout = out + (long)TT*BATCH*PV;
    vocab_mma<<<dim3(WV/128, TT*BATCH/128), 256>>>(he_bf, wemb_bf, word_proj2_b, wout);
    word_lsm<<<TT*BATCH, 256>>>(wout);
}

// round 8
// speedup vs baseline: 1.8698x; 1.8698x over previous
#include <cuda_runtime.h>
#include <cuda_bf16.h>
#include <math.h>

#define TT 64
#define BATCH 32
#define PE 128
#define WE 512
#define PH 256
#define WH 1024
#define PV 48
#define WV 32000
#define GRID 148
#define TPB 512
#define SLDA 1032   // bf16 elems per staged row (2064B: +16B pad -> ldmatrix conflict-free)

// ---------------- fp32 scratch ----------------
#define SZ_PEMB  (TT*BATCH*PE)
#define SZ_WEMB  (TT*BATCH*WE)
#define SZ_GPSEQ (TT*BATCH*4*PH)
#define SZ_GWSEQ (TT*BATCH*4*WH)
#define OFF_PEMB  0
#define OFF_WEMB  (OFF_PEMB + SZ_PEMB)
#define OFF_GPSEQ (OFF_WEMB + SZ_WEMB)
#define OFF_GWSEQ (OFF_GPSEQ + SZ_GPSEQ)
#define OFF_PC    (OFF_GWSEQ + SZ_GWSEQ)
#define OFF_WC0   (OFF_PC + BATCH*PH)
#define OFF_WC1   (OFF_WC0 + BATCH*WH)
#define OFF_WG0H  (OFF_WC1 + BATCH*WH)
#define OFF_WG1H  (OFF_WG0H + BATCH*4*WH)
#define OFF_PHSEQ (OFF_WG1H + BATCH*4*WH)
#define OFF_WHSEQ (OFF_PHSEQ + TT*BATCH*PH)
#define OFF_HE    (OFF_WHSEQ + TT*BATCH*WH)
#define SCRATCH_TOTAL (OFF_HE + TT*BATCH*WE)

__device__ float g_scratch[SCRATCH_TOTAL];
__device__ unsigned g_bar_cnt = 0;
__device__ unsigned g_bar_gen = 0;

// bf16 weights (compact [N,K]) + states
__device__ __nv_bfloat16 g_bw2p  [1024*1024];
__device__ __nv_bfloat16 g_bwhh1 [4096*1024];
__device__ __nv_bfloat16 g_bwhh0 [4096*1024];
__device__ __nv_bfloat16 g_bpih  [1024*1024];
__device__ __nv_bfloat16 g_bphh  [1024*256];
__device__ __nv_bfloat16 g_bp2w  [256*256];
__device__ __nv_bfloat16 g_bwih0p[4096*256];
__device__ __nv_bfloat16 g_bwih1 [4096*1024];
__device__ __nv_bfloat16 g_bwh1  [32*1024];
__device__ __nv_bfloat16 g_bwh0  [32*1024];
__device__ __nv_bfloat16 g_bph   [2][32*256];
__device__ __nv_bfloat16 g_blastw[32*1024];
__device__ __nv_bfloat16 g_wemb_bf[(size_t)WV*WE];
__device__ __nv_bfloat16 g_he_bf[(size_t)TT*BATCH*WE];

// smem: sA1, sA2 (32*SLDA bf16 each), red (16 warps * 32 lanes * 17 floats)
#define SMEM_A1  0
#define SMEM_A2  66048
#define SMEM_RED 132096
#define SMEM_DYN 166912

__device__ __forceinline__ float sigf(float x) { return 1.f/(1.f+expf(-x)); }

__device__ __forceinline__ void mma16816(float* c, const unsigned* a, const unsigned* b)
{
    asm volatile("mma.sync.aligned.m16n8k16.row.col.f32.bf16.bf16.f32 "
        "{%0,%1,%2,%3}, {%4,%5,%6,%7}, {%8,%9}, {%0,%1,%2,%3};"
        : "+f"(c[0]), "+f"(c[1]), "+f"(c[2]), "+f"(c[3])
        : "r"(a[0]), "r"(a[1]), "r"(a[2]), "r"(a[3]), "r"(b[0]), "r"(b[1]));
}
__device__ __forceinline__ void ldsm4(unsigned* r, const void* p)
{
    unsigned ad = (unsigned)__cvta_generic_to_shared(p);
    asm volatile("ldmatrix.sync.aligned.m8n8.x4.shared.b16 {%0,%1,%2,%3}, [%4];"
        : "=r"(r[0]), "=r"(r[1]), "=r"(r[2]), "=r"(r[3]) : "r"(ad));
}

// ---------------- init ----------------
__global__ void init_kernel(const int* __restrict__ pos, const int* __restrict__ word,
                            const float* __restrict__ pos_emb, const float* __restrict__ word_emb,
                            float* __restrict__ S)
{
    int i = blockIdx.x*blockDim.x + threadIdx.x;
    int st = gridDim.x*blockDim.x;
    float* pemb = S + OFF_PEMB;
    float* wemb = S + OFF_WEMB;
    for (int x = i; x < TT*BATCH*PE; x += st) { int tb = x/PE; pemb[x] = pos_emb[pos[tb]*PE + x - tb*PE]; }
    for (int x = i; x < TT*BATCH*WE; x += st) { int tb = x/WE; wemb[x] = word_emb[word[tb]*WE + x - tb*WE]; }
    for (int x = i; x < BATCH*PH; x += st) S[OFF_PC + x] = 0.f;
    for (int x = i; x < 2*BATCH*WH; x += st) S[OFF_WC0 + x] = 0.f;
    unsigned* z1 = (unsigned*)g_bwh1; unsigned* z2 = (unsigned*)g_bwh0; unsigned* z3 = (unsigned*)g_bph;
    for (int x = i; x < 16384; x += st) { z1[x] = 0u; z2[x] = 0u; }
    for (int x = i; x < 8192; x += st) z3[x] = 0u;
}

// ---------------- conversions ----------------
__global__ void conv_bf16(const float* __restrict__ src, __nv_bfloat16* __restrict__ dst, int n4)
{
    int i = blockIdx.x*blockDim.x + threadIdx.x;
    int st = gridDim.x*blockDim.x;
    const float4* s4 = (const float4*)src;
    for (; i < n4; i += st) {
        float4 v = s4[i];
        *(__nv_bfloat162*)(dst + (size_t)i*4)   = __floats2bfloat162_rn(v.x, v.y);
        *(__nv_bfloat162*)(dst + (size_t)i*4+2) = __floats2bfloat162_rn(v.z, v.w);
    }
}
__global__ void conv_w(const float* __restrict__ src, __nv_bfloat16* __restrict__ dst,
                       int rows, int src_ld, int col0, int cols)
{
    int half = cols >> 1;
    long tot = (long)rows*half;
    for (long i = (long)blockIdx.x*blockDim.x + threadIdx.x; i < tot; i += (long)gridDim.x*blockDim.x) {
        int r = (int)(i/half), c = (int)(i - (long)r*half)*2;
        float2 v = *(const float2*)&src[(size_t)r*src_ld + col0 + c];
        *(__nv_bfloat162*)&dst[(size_t)r*cols + c] = __floats2bfloat162_rn(v.x, v.y);
    }
}

// ---------------- grid barrier ----------------
__device__ __forceinline__ void grid_bar()
{
    __threadfence();
    __syncthreads();
    if (threadIdx.x == 0) {
        volatile unsigned* gen = &g_bar_gen;
        unsigned g = *gen;
        unsigned a = atomicAdd(&g_bar_cnt, 1u);
        if (a == GRID-1u) { g_bar_cnt = 0u; __threadfence(); atomicAdd(&g_bar_gen, 1u); }
        else while (*gen == g) __nanosleep(32);
    }
    __syncthreads();
    __threadfence();
}

// ---------------- persist building blocks ----------------
__device__ __forceinline__ void stage_bf16(const __nv_bfloat16* __restrict__ A, int K,
                                           __nv_bfloat16* __restrict__ sd)
{
    int Kc = K >> 3;
    for (int i = threadIdx.x; i < 32*Kc; i += TPB) {
        int row = i/Kc, c = i - row*Kc;
        *(uint4*)&sd[row*SLDA + (c<<3)] = *(const uint4*)&A[row*K + (c<<3)];
    }
}
// m32 x n16 tile: acc[mf*8 + f*4 + c]
__device__ __forceinline__ void gen_accum(const __nv_bfloat16* __restrict__ sAp,
    const __nv_bfloat16* __restrict__ Wp, int Kld, int nbase, int kb, int ke,
    float* acc, int lane)
{
    const __nv_bfloat16* ar = sAp + (lane&15)*SLDA + 8*(lane>>4);
    const __nv_bfloat16* w0 = Wp + (size_t)(nbase + (lane>>2))*Kld + 2*(lane&3);
    const __nv_bfloat16* w1 = w0 + (size_t)8*Kld;
    #pragma unroll 4
    for (int kk = kb; kk < ke; kk++) {
        int k0 = kk*16;
        unsigned a0[4], a1[4], b0[2], b1[2];
        ldsm4(a0, ar + k0);
        ldsm4(a1, ar + 16*SLDA + k0);
        b0[0] = *(const unsigned*)(w0 + k0); b0[1] = *(const unsigned*)(w0 + k0 + 8);
        b1[0] = *(const unsigned*)(w1 + k0); b1[1] = *(const unsigned*)(w1 + k0 + 8);
        mma16816(acc+0, a0, b0);  mma16816(acc+8, a1, b0);
        mma16816(acc+4, a0, b1);  mma16816(acc+12, a1, b1);
    }
}
__device__ __forceinline__ void red_store(float* red, int wrp, int lane, const float* acc)
{
    float* p = red + (wrp*32 + lane)*17;
    #pragma unroll
    for (int i = 0; i < 16; i++) p[i] = acc[i];
}
__device__ __forceinline__ float red_gather(const float* red, int ts, int li, int ai)
{
    const float* p = red + (ts*4*32 + li)*17 + ai;
    return p[0] + p[32*17] + p[2*32*17] + p[3*32*17];
}
// element (b, jl) of an m32 x n16 tile -> (lane, acc idx)
__device__ __forceinline__ void elem_map(int b, int jl, int& li, int& ai)
{
    li = (b&7)*4 + ((jl&7)>>1);
    ai = (b>>4)*8 + (jl>>3)*4 + ((b>>3)&1)*2 + (jl&1);
}

// ---------------- persistent tensor-core sequential phase ----------------
__global__ __launch_bounds__(TPB, 1) void persist_kernel(
    const float* __restrict__ w2p_b, const float* __restrict__ p2w_b,
    const float* __restrict__ w_bih1, const float* __restrict__ w_bhh1,
    float* __restrict__ S)
{
    extern __shared__ char smem[];
    __nv_bfloat16* sA1 = (__nv_bfloat16*)(smem + SMEM_A1);
    __nv_bfloat16* sA2 = (__nv_bfloat16*)(smem + SMEM_A2);
    float* red = (float*)(smem + SMEM_RED);

    float* gpseq = S + OFF_GPSEQ;
    float* gwseq = S + OFF_GWSEQ;
    float* pc    = S + OFF_PC;
    float* wc0   = S + OFF_WC0;
    float* wc1   = S + OFF_WC1;
    float* wg0h  = S + OFF_WG0H;
    float* wg1h  = S + OFF_WG1H;
    float* phseq = S + OFF_PHSEQ;
    float* whseq = S + OFF_WHSEQ;

    int lane = threadIdx.x & 31;
    int wrp  = threadIdx.x >> 5;
    int ts   = wrp >> 2;      // tile slot / gate
    int ks   = wrp & 3;       // k slice
    int pp = 0;

    for (int t = 0; t < TT; t++) {
        // ===== S1: lastw(tanh), wg1h, wg0h — 576 tiles / 144 blocks =====
        if (blockIdx.x < 144) {
            stage_bf16(g_bwh1, 1024, sA1);
            stage_bf16(g_bwh0, 1024, sA2);
            __syncthreads();
            int tile = blockIdx.x*4 + ts;
            const __nv_bfloat16 *Ap, *Wp; int n0, mode;
            if (tile < 64)       { Ap = sA1; Wp = g_bw2p;  n0 = tile*16;       mode = 0; }
            else if (tile < 320) { Ap = sA1; Wp = g_bwhh1; n0 = (tile-64)*16;  mode = 1; }
            else                 { Ap = sA2; Wp = g_bwhh0; n0 = (tile-320)*16; mode = 2; }
            float acc[16];
            #pragma unroll
            for (int i = 0; i < 16; i++) acc[i] = 0.f;
            gen_accum(Ap, Wp, 1024, n0, ks*16, ks*16+16, acc, lane);
            red_store(red, wrp, lane, acc);
            __syncthreads();
            {
                int e = threadIdx.x, b = e&31, jl = e>>5, li, ai;
                elem_map(b, jl, li, ai);
                #pragma unroll
                for (int tt2 = 0; tt2 < 4; tt2++) {
                    int tl = blockIdx.x*4 + tt2;
                    float v = red_gather(red, tt2, li, ai);
                    if (tl < 64) {
                        int n = tl*16 + jl;
                        g_blastw[b*1024 + n] = __float2bfloat16(tanhf(v + w2p_b[n]));
                    } else if (tl < 320) {
                        int n = (tl-64)*16 + jl;
                        wg1h[b*4096 + n] = v;
                    } else {
                        int n = (tl-320)*16 + jl;
                        wg0h[b*4096 + n] = v;
                    }
                }
            }
        }
        grid_bar();

        // ===== S2: POS gates + cell — 16 blocks (j0 = blk*16), K = 1024(lastw) + 256(ph) =====
        if (blockIdx.x < 16) {
            stage_bf16(g_blastw, 1024, sA1);
            stage_bf16(g_bph[pp], 256, sA2);
            __syncthreads();
            int j0 = blockIdx.x*16;
            int nbase = ts*PH + j0;       // ts = gate
            float acc[16];
            #pragma unroll
            for (int i = 0; i < 16; i++) acc[i] = 0.f;
            int sb = ks*20, se = sb + 20;
            if (sb < 64) gen_accum(sA1, g_bpih, 1024, nbase, sb, se < 64 ? se : 64, acc, lane);
            if (se > 64) gen_accum(sA2, g_bphh, 256, nbase, sb > 64 ? sb-64 : 0, se-64, acc, lane);
            red_store(red, wrp, lane, acc);
            __syncthreads();
            {
                int e = threadIdx.x, b = e&31, jl = e>>5, li, ai;
                elem_map(b, jl, li, ai);
                int j = j0 + jl;
                const float* pre = gpseq + ((size_t)t*BATCH + b)*(4*PH) + j;
                float gi = red_gather(red, 0, li, ai) + pre[0*PH];
                float gf = red_gather(red, 1, li, ai) + pre[1*PH];
                float gg = red_gather(red, 2, li, ai) + pre[2*PH];
                float go = red_gather(red, 3, li, ai) + pre[3*PH];
                int idx = b*PH + j;
                float cn = sigf(gf)*pc[idx] + sigf(gi)*tanhf(gg);
                float hn = sigf(go)*tanhf(cn);
                pc[idx] = cn;
                g_bph[pp^1][idx] = __float2bfloat16(hn);
                phseq[((size_t)t*BATCH + b)*PH + j] = hn;
            }
        }
        grid_bar();

        // ===== S4: lastp prologue + WORD L0 gates + cell — 64 blocks (j0 = blk*16) =====
        if (blockIdx.x < 64) {
            stage_bf16(g_bph[pp^1], 256, sA2);
            __syncthreads();
            {   // lastp = tanh(ph_new @ p2w^T + b) -> sA1 (staged layout), one n16 tile/warp
                int n0 = wrp*16;
                float acc[16];
                #pragma unroll
                for (int i = 0; i < 16; i++) acc[i] = 0.f;
                gen_accum(sA2, g_bp2w, 256, n0, 0, 16, acc, lane);
                #pragma unroll
                for (int mf = 0; mf < 2; mf++)
                #pragma unroll
                for (int f = 0; f < 2; f++) {
                    int rb = mf*16 + (lane>>2);
                    int cl = n0 + f*8 + 2*(lane&3);
                    float b0 = p2w_b[cl], b1 = p2w_b[cl+1];
                    const float* a = acc + mf*8 + f*4;
                    *(__nv_bfloat162*)&sA1[rb*SLDA + cl] =
                        __floats2bfloat162_rn(tanhf(a[0]+b0), tanhf(a[1]+b1));
                    *(__nv_bfloat162*)&sA1[(rb+8)*SLDA + cl] =
                        __floats2bfloat162_rn(tanhf(a[2]+b0), tanhf(a[3]+b1));
                }
            }
            __syncthreads();
            int j0 = blockIdx.x*16;
            int nbase = ts*WH + j0;
            float acc[16];
            #pragma unroll
            for (int i = 0; i < 16; i++) acc[i] = 0.f;
            gen_accum(sA1, g_bwih0p, 256, nbase, ks*4, ks*4+4, acc, lane);
            red_store(red, wrp, lane, acc);
            __syncthreads();
            {
                int e = threadIdx.x, b = e&31, jl = e>>5, li, ai;
                elem_map(b, jl, li, ai);
                int j = j0 + jl;
                const float* pre = gwseq + ((size_t)t*BATCH + b)*(4*WH) + j;
                const float* hid = wg0h + (size_t)b*4096 + j;
                float gi = red_gather(red, 0, li, ai) + pre[0*WH] + hid[0*WH];
                float gf = red_gather(red, 1, li, ai) + pre[1*WH] + hid[1*WH];
                float gg = red_gather(red, 2, li, ai) + pre[2*WH] + hid[2*WH];
                float go = red_gather(red, 3, li, ai) + pre[3*WH] + hid[3*WH];
                int idx = b*WH + j;
                float cn = sigf(gf)*wc0[idx] + sigf(gi)*tanhf(gg);
                float hn = sigf(go)*tanhf(cn);
                wc0[idx] = cn;
                g_bwh0[idx] = __float2bfloat16(hn);
            }
        }
        grid_bar();

        // ===== S5: WORD L1 gates + cell — 64 blocks, K=1024 =====
        if (blockIdx.x < 64) {
            stage_bf16(g_bwh0, 1024, sA1);
            __syncthreads();
            int j0 = blockIdx.x*16;
            int nbase = ts*WH + j0;
            float acc[16];
            #pragma unroll
            for (int i = 0; i < 16; i++) acc[i] = 0.f;
            gen_accum(sA1, g_bwih1, 1024, nbase, ks*16, ks*16+16, acc, lane);
            red_store(red, wrp, lane, acc);
            __syncthreads();
            {
                int e = threadIdx.x, b = e&31, jl = e>>5, li, ai;
                elem_map(b, jl, li, ai);
                int j = j0 + jl;
                const float* hid = wg1h + (size_t)b*4096 + j;
                float gi = red_gather(red, 0, li, ai) + hid[0*WH] + w_bih1[0*WH+j] + w_bhh1[0*WH+j];
                float gf = red_gather(red, 1, li, ai) + hid[1*WH] + w_bih1[1*WH+j] + w_bhh1[1*WH+j];
                float gg = red_gather(red, 2, li, ai) + hid[2*WH] + w_bih1[2*WH+j] + w_bhh1[2*WH+j];
                float go = red_gather(red, 3, li, ai) + hid[3*WH] + w_bih1[3*WH+j] + w_bhh1[3*WH+j];
                int idx = b*WH + j;
                float cn = sigf(gf)*wc1[idx] + sigf(gi)*tanhf(gg);
                float hn = sigf(go)*tanhf(cn);
                wc1[idx] = cn;
                g_bwh1[idx] = __float2bfloat16(hn);
                whseq[((size_t)t*BATCH + b)*WH + j] = hn;
            }
        }
        grid_bar();
        pp ^= 1;
    }
}

// ---------------- fp32 big GEMM (precomputes + proj1) ----------------
__global__ __launch_bounds__(256) void big_gemm(const float* __restrict__ A, int lda,
                                                const float* __restrict__ W, int ldw, int wcol,
                                                const float* __restrict__ bias1,
                                                const float* __restrict__ bias2,
                                                float* __restrict__ C, long ldc, int K)
{
    __shared__ float sAa[16][132];
    __shared__ float sW[16][68];
    int tx = threadIdx.x & 15, ty = threadIdx.x >> 4;
    int bm = blockIdx.y*128, bn = blockIdx.x*64;
    float acc[8][4];
    #pragma unroll
    for (int i = 0; i < 8; i++)
        #pragma unroll
        for (int j = 0; j < 4; j++) acc[i][j] = 0.f;
    for (int kt = 0; kt < K; kt += 16) {
        __syncthreads();
        #pragma unroll
        for (int i = 0; i < 2; i++) {
            int f = threadIdx.x + i*256;
            int row = f >> 2, kq = (f&3)*4;
            float4 v = *(const float4*)(A + (long)(bm+row)*lda + kt + kq);
            sAa[kq][row] = v.x; sAa[kq+1][row] = v.y; sAa[kq+2][row] = v.z; sAa[kq+3][row] = v.w;
        }
        {
            int f = threadIdx.x;
            int row = f >> 2, kq = (f&3)*4;
            float4 v = *(const float4*)(W + (long)(bn+row)*ldw + wcol + kt + kq);
            sW[kq][row] = v.x; sW[kq+1][row] = v.y; sW[kq+2][row] = v.z; sW[kq+3][row] = v.w;
        }
        __syncthreads();
        #pragma unroll
        for (int k = 0; k < 16; k++) {
            float4 a0 = *(float4*)&sAa[k][ty*8];
            float4 a1 = *(float4*)&sAa[k][ty*8+4];
            float4 w  = *(float4*)&sW[k][tx*4];
            float am[8] = {a0.x,a0.y,a0.z,a0.w,a1.x,a1.y,a1.z,a1.w};
            float wn[4] = {w.x,w.y,w.z,w.w};
            #pragma unroll
            for (int i = 0; i < 8; i++)
                #pragma unroll
                for (int j = 0; j < 4; j++)
                    acc[i][j] = fmaf(am[i], wn[j], acc[i][j]);
        }
    }
    float bv[4];
    #pragma unroll
    for (int j = 0; j < 4; j++) {
        int nn = bn + tx*4 + j;
        bv[j] = (bias1 ? bias1[nn] : 0.f) + (bias2 ? bias2[nn] : 0.f);
    }
    #pragma unroll
    for (int i = 0; i < 8; i++) {
        int m = bm + ty*8 + i;
        float4 o;
        o.x = acc[i][0]+bv[0]; o.y = acc[i][1]+bv[1]; o.z = acc[i][2]+bv[2]; o.w = acc[i][3]+bv[3];
        *(float4*)(C + (long)m*ldc + bn + tx*4) = o;
    }
}

// ---------------- tensor-core vocab GEMM ----------------
__global__ __launch_bounds__(256) void vocab_mma(const __nv_bfloat16* __restrict__ Abf,
                                                 const __nv_bfloat16* __restrict__ Bbf,
                                                 const float* __restrict__ bias,
                                                 float* __restrict__ C)
{
    __shared__ __nv_bfloat16 sAm[128][40];
    __shared__ __nv_bfloat16 sBm[128][40];
    int tid = threadIdx.x, lane = tid&31, wid = tid>>5;
    int wm = wid>>2, wn = wid&3;
    int bm = blockIdx.y*128, bn = blockIdx.x*128;
    float acc[4][4][4] = {};
    for (int kt = 0; kt < WE; kt += 32) {
        __syncthreads();
        #pragma unroll
        for (int c = 0; c < 2; c++) {
            int ch = tid + c*256;
            int row = ch>>2, seg = (ch&3)*8;
            *(uint4*)&sAm[row][seg] = *(const uint4*)&Abf[(size_t)(bm+row)*WE + kt + seg];
            *(uint4*)&sBm[row][seg] = *(const uint4*)&Bbf[(size_t)(bn+row)*WE + kt + seg];
        }
        __syncthreads();
        #pragma unroll
        for (int k16 = 0; k16 < 2; k16++) {
            unsigned afrag[4][4], bfrag[4][2];
            #pragma unroll
            for (int mf = 0; mf < 4; mf++)
                ldsm4(afrag[mf], &sAm[wm*64 + mf*16 + (lane&15)][k16*16 + (lane>>4)*8]);
            #pragma unroll
            for (int np = 0; np < 2; np++) {
                unsigned r[4];
                ldsm4(r, &sBm[wn*32 + np*16 + (lane&7) + ((lane>>4)<<3)][k16*16 + (((lane>>3)&1)<<3)]);
                bfrag[np*2][0] = r[0]; bfrag[np*2][1] = r[1];
                bfrag[np*2+1][0] = r[2]; bfrag[np*2+1][1] = r[3];
            }
            #pragma unroll
            for (int mf = 0; mf < 4; mf++)
                #pragma unroll
                for (int nf = 0; nf < 4; nf++)
                    mma16816(acc[mf][nf], afrag[mf], bfrag[nf]);
        }
    }
    int tg = lane>>2, tc = (lane&3)*2;
    #pragma unroll
    for (int nf = 0; nf < 4; nf++) {
        int n = bn + wn*32 + nf*8 + tc;
        float b0 = bias[n], b1 = bias[n+1];
        #pragma unroll
        for (int mf = 0; mf < 4; mf++) {
            int m0 = bm + wm*64 + mf*16 + tg;
            float2 v0 = { acc[mf][nf][0]+b0, acc[mf][nf][1]+b1 };
            float2 v1 = { acc[mf][nf][2]+b0, acc[mf][nf][3]+b1 };
            *(float2*)&C[(size_t)m0*WV + n] = v0;
            *(float2*)&C[(size_t)(m0+8)*WV + n] = v1;
        }
    }
}

// ---------------- pos projection + log_softmax ----------------
__global__ void pos_out_kernel(const float* __restrict__ phseq, const float* __restrict__ proj_W,
                               const float* __restrict__ proj_b, float* __restrict__ out)
{
    int row = blockIdx.x;
    const float* h = phseq + row*PH;
    __shared__ float sh[PH];
    __shared__ float logits[PV];
    __shared__ float lse;
    for (int i = threadIdx.x; i < PH; i += 64) sh[i] = h[i];
    __syncthreads();
    if (threadIdx.x < PV) {
        float s = proj_b[threadIdx.x];
        const float* wr = proj_W + threadIdx.x*PH;
        #pragma unroll 4
        for (int k = 0; k < PH; k++) s += sh[k]*wr[k];
        logits[threadIdx.x] = s;
    }
    __syncthreads();
    if (threadIdx.x == 0) {
        float m = -1e30f;
        for (int i = 0; i < PV; i++) m = fmaxf(m, logits[i]);
        float ssum = 0.f;
        for (int i = 0; i < PV; i++) ssum += expf(logits[i]-m);
        lse = m + logf(ssum);
    }
    __syncthreads();
    if (threadIdx.x < PV) out[row*PV + threadIdx.x] = logits[threadIdx.x] - lse;
}

// ---------------- in-place log_softmax (word) ----------------
__global__ void word_lsm(float* __restrict__ out)
{
    int row = blockIdx.x;
    float* r = out + (long)row*WV;
    float m = -1e30f, s = 0.f;
    for (int i = threadIdx.x; i < WV; i += blockDim.x) {
        float v = r[i];
        if (v > m) { s = s*expf(m-v) + 1.f; m = v; } else s += expf(v-m);
    }
    __shared__ float sm[256], ss[256];
    sm[threadIdx.x] = m; ss[threadIdx.x] = s;
    __syncthreads();
    for (int off = 128; off > 0; off >>= 1) {
        if (threadIdx.x < off) {
            float m1 = sm[threadIdx.x], s1 = ss[threadIdx.x];
            float m2 = sm[threadIdx.x+off], s2 = ss[threadIdx.x+off];
            float mm = fmaxf(m1, m2);
            sm[threadIdx.x] = mm;
            ss[threadIdx.x] = s1*expf(m1-mm) + s2*expf(m2-mm);
        }
        __syncthreads();
    }
    float lse = sm[0] + logf(ss[0]);
    for (int i = threadIdx.x; i < WV; i += blockDim.x) r[i] -= lse;
}

// ---------------- host ----------------
extern "C" void kernel_launch(void* const* d_in, const int* in_sizes, int n_in,
                              void* d_out, int out_size)
{
    (void)in_sizes; (void)n_in; (void)out_size;
    const int*   pos          = (const int*)  d_in[0];
    const int*   word         = (const int*)  d_in[1];
    const float* pos_emb_W    = (const float*)d_in[2];
    const float* word_emb_W   = (const float*)d_in[3];
    const float* w2p_W        = (const float*)d_in[4];
    const float* w2p_b        = (const float*)d_in[5];
    const float* p2w_W        = (const float*)d_in[6];
    const float* p2w_b        = (const float*)d_in[7];
    const float* p_Wih0       = (const float*)d_in[8];
    const float* p_Whh0       = (const float*)d_in[9];
    const float* p_bih0       = (const float*)d_in[10];
    const float* p_bhh0       = (const float*)d_in[11];
    const float* w_Wih0       = (const float*)d_in[12];
    const float* w_Whh0       = (const float*)d_in[13];
    const float* w_bih0       = (const float*)d_in[14];
    const float* w_bhh0       = (const float*)d_in[15];
    const float* w_Wih1       = (const float*)d_in[16];
    const float* w_Whh1       = (const float*)d_in[17];
    const float* w_bih1       = (const float*)d_in[18];
    const float* w_bhh1       = (const float*)d_in[19];
    const float* pos_proj_W   = (const float*)d_in[20];
    const float* pos_proj_b   = (const float*)d_in[21];
    const float* word_proj1_W = (const float*)d_in[22];
    const float* word_proj1_b = (const float*)d_in[23];
    const float* word_proj2_b = (const float*)d_in[24];
    float* out = (float*)d_out;

    float* S; cudaGetSymbolAddress((void**)&S, g_scratch);
    __nv_bfloat16 *wemb_bf, *he_bf, *bw2p, *bwhh1, *bwhh0, *bpih, *bphh, *bp2w, *bwih0p, *bwih1;
    cudaGetSymbolAddress((void**)&wemb_bf, g_wemb_bf);
    cudaGetSymbolAddress((void**)&he_bf, g_he_bf);
    cudaGetSymbolAddress((void**)&bw2p, g_bw2p);
    cudaGetSymbolAddress((void**)&bwhh1, g_bwhh1);
    cudaGetSymbolAddress((void**)&bwhh0, g_bwhh0);
    cudaGetSymbolAddress((void**)&bpih, g_bpih);
    cudaGetSymbolAddress((void**)&bphh, g_bphh);
    cudaGetSymbolAddress((void**)&bp2w, g_bp2w);
    cudaGetSymbolAddress((void**)&bwih0p, g_bwih0p);
    cudaGetSymbolAddress((void**)&bwih1, g_bwih1);

    float* pemb  = S + OFF_PEMB;
    float* wemb  = S + OFF_WEMB;
    float* gpseq = S + OFF_GPSEQ;
    float* gwseq = S + OFF_GWSEQ;
    float* phseq = S + OFF_PHSEQ;
    float* whseq = S + OFF_WHSEQ;
    float* he    = S + OFF_HE;

    static bool attr_set = false;
    if (!attr_set) {
        cudaFuncSetAttribute(persist_kernel, cudaFuncAttributeMaxDynamicSharedMemorySize, SMEM_DYN);
        attr_set = true;
    }

    init_kernel<<<256, 256>>>(pos, word, pos_emb_W, word_emb_W, S);
    conv_bf16<<<2048, 256>>>(word_emb_W, wemb_bf, (int)((size_t)WV*WE/4));

    // weight conversions (compact bf16 [N,K])
    conv_w<<<256, 256>>>(w2p_W,   bw2p,   1024, 1024, 0,   1024);
    conv_w<<<256, 256>>>(w_Whh1,  bwhh1,  4096, 1024, 0,   1024);
    conv_w<<<256, 256>>>(w_Whh0,  bwhh0,  4096, 1024, 0,   1024);
    conv_w<<<256, 256>>>(p_Wih0,  bpih,   1024, 1152, 128, 1024);
    conv_w<<<256, 256>>>(p_Whh0,  bphh,   1024, 256,  0,   256);
    conv_w<<<256, 256>>>(p2w_W,   bp2w,   256,  256,  0,   256);
    conv_w<<<256, 256>>>(w_Wih0,  bwih0p, 4096, 768,  512, 256);
    conv_w<<<256, 256>>>(w_Wih1,  bwih1,  4096, 1024, 0,   1024);

    // input-side gate precomputes
    big_gemm<<<dim3(4*PH/64, TT*BATCH/128), 256>>>(pemb, PE, p_Wih0, PE+WH, 0,
                                                   p_bih0, p_bhh0, gpseq, 4*PH, PE);
    big_gemm<<<dim3(4*WH/64, TT*BATCH/128), 256>>>(wemb, WE, w_Wih0, WE+PH, 0,
                                                   w_bih0, w_bhh0, gwseq, 4*WH, WE);

    persist_kernel<<<GRID, TPB, SMEM_DYN>>>(w2p_b, p2w_b, w_bih1, w_bhh1, S);

    pos_out_kernel<<<TT*BATCH, 64>>>(phseq, pos_proj_W, pos_proj_b, out);

    big_gemm<<<dim3(WE/64, TT*BATCH/128), 256>>>(whseq, WH, word_proj1_W, WH, 0,
                                                 word_proj1_b, nullptr, he, WE, WH);
    conv_bf16<<<1024, 256>>>(he, he_bf, (int)((size_t)TT*BATCH*WE/4));

    float* wout = out + (long)TT*BATCH*PV;
    vocab_mma<<<dim3(WV/128, TT*BATCH/128), 256>>>(he_bf, wemb_bf, word_proj2_b, wout);
    word_lsm<<<TT*BATCH, 256>>>(wout);
}

// round 9
// speedup vs baseline: 2.4255x; 1.2972x over previous
#include <cuda_runtime.h>
#include <cuda_bf16.h>
#include <math.h>

#define TT 64
#define BATCH 32
#define PE 128
#define WE 512
#define PH 256
#define WH 1024
#define PV 48
#define WV 32000
#define GRID 148
#define TPB 512
#define SLDA 1032

// ---------------- fp32 scratch ----------------
#define OFF_GPSEQ 0
#define OFF_GWSEQ (OFF_GPSEQ + TT*BATCH*4*PH)
#define OFF_PC    (OFF_GWSEQ + TT*BATCH*4*WH)
#define OFF_WC0   (OFF_PC + BATCH*PH)
#define OFF_WC1   (OFF_WC0 + BATCH*WH)
#define OFF_WG0H  (OFF_WC1 + BATCH*WH)
#define OFF_WG1H  (OFF_WG0H + BATCH*4*WH)
#define OFF_PHSEQ (OFF_WG1H + BATCH*4*WH)
#define SCRATCH_TOTAL (OFF_PHSEQ + TT*BATCH*PH)

__device__ float g_scratch[SCRATCH_TOTAL];
__device__ unsigned g_bar_cnt = 0;
__device__ unsigned g_bar_gen = 0;

// bf16 weights (compact [N,K]) + states + activations
__device__ __nv_bfloat16 g_bw2p  [1024*1024];
__device__ __nv_bfloat16 g_bwhh1 [4096*1024];
__device__ __nv_bfloat16 g_bwhh0 [4096*1024];
__device__ __nv_bfloat16 g_bpih  [1024*1024];
__device__ __nv_bfloat16 g_bphh  [1024*256];
__device__ __nv_bfloat16 g_bp2w  [256*256];
__device__ __nv_bfloat16 g_bwih0p[4096*256];
__device__ __nv_bfloat16 g_bwih1 [4096*1024];
__device__ __nv_bfloat16 g_bpihe [1024*128];
__device__ __nv_bfloat16 g_bwih0e[4096*512];
__device__ __nv_bfloat16 g_bproj1[512*1024];
__device__ __nv_bfloat16 g_bwh1  [32*1024];
__device__ __nv_bfloat16 g_bwh0  [32*1024];
__device__ __nv_bfloat16 g_bph   [2][32*256];
__device__ __nv_bfloat16 g_blastw[32*1024];
__device__ __nv_bfloat16 g_pembin[TT*BATCH*PE];
__device__ __nv_bfloat16 g_wembin[TT*BATCH*WE];
__device__ __nv_bfloat16 g_whseq_bf[(size_t)TT*BATCH*WH];
__device__ __nv_bfloat16 g_wemb_bf[(size_t)WV*WE];
__device__ __nv_bfloat16 g_he_bf[(size_t)TT*BATCH*WE];

#define SMEM_A1  0
#define SMEM_A2  66048
#define SMEM_RED 132096
#define SMEM_DYN 166912

__device__ __forceinline__ float sigf(float x) { return 1.f/(1.f+expf(-x)); }

__device__ __forceinline__ void mma16816(float* c, const unsigned* a, const unsigned* b)
{
    asm volatile("mma.sync.aligned.m16n8k16.row.col.f32.bf16.bf16.f32 "
        "{%0,%1,%2,%3}, {%4,%5,%6,%7}, {%8,%9}, {%0,%1,%2,%3};"
        : "+f"(c[0]), "+f"(c[1]), "+f"(c[2]), "+f"(c[3])
        : "r"(a[0]), "r"(a[1]), "r"(a[2]), "r"(a[3]), "r"(b[0]), "r"(b[1]));
}
__device__ __forceinline__ void ldsm4(unsigned* r, const void* p)
{
    unsigned ad = (unsigned)__cvta_generic_to_shared(p);
    asm volatile("ldmatrix.sync.aligned.m8n8.x4.shared.b16 {%0,%1,%2,%3}, [%4];"
        : "=r"(r[0]), "=r"(r[1]), "=r"(r[2]), "=r"(r[3]) : "r"(ad));
}

// ---------------- init: gather embeddings to bf16, zero states ----------------
__global__ void init_kernel(const int* __restrict__ pos, const int* __restrict__ word,
                            const float* __restrict__ pos_emb, const float* __restrict__ word_emb,
                            float* __restrict__ S)
{
    int i = blockIdx.x*blockDim.x + threadIdx.x;
    int st = gridDim.x*blockDim.x;
    for (int x = i; x < TT*BATCH*PE; x += st) {
        int tb = x/PE;
        g_pembin[x] = __float2bfloat16(pos_emb[pos[tb]*PE + x - tb*PE]);
    }
    for (int x = i; x < TT*BATCH*WE; x += st) {
        int tb = x/WE;
        g_wembin[x] = __float2bfloat16(word_emb[word[tb]*WE + x - tb*WE]);
    }
    for (int x = i; x < BATCH*PH; x += st) S[OFF_PC + x] = 0.f;
    for (int x = i; x < 2*BATCH*WH; x += st) S[OFF_WC0 + x] = 0.f;
    unsigned* z1 = (unsigned*)g_bwh1; unsigned* z2 = (unsigned*)g_bwh0; unsigned* z3 = (unsigned*)g_bph;
    for (int x = i; x < 16384; x += st) { z1[x] = 0u; z2[x] = 0u; }
    for (int x = i; x < 8192; x += st) z3[x] = 0u;
}

// ---------------- conversions ----------------
__global__ void conv_bf16(const float* __restrict__ src, __nv_bfloat16* __restrict__ dst, int n4)
{
    int i = blockIdx.x*blockDim.x + threadIdx.x;
    int st = gridDim.x*blockDim.x;
    const float4* s4 = (const float4*)src;
    for (; i < n4; i += st) {
        float4 v = s4[i];
        *(__nv_bfloat162*)(dst + (size_t)i*4)   = __floats2bfloat162_rn(v.x, v.y);
        *(__nv_bfloat162*)(dst + (size_t)i*4+2) = __floats2bfloat162_rn(v.z, v.w);
    }
}
__global__ void conv_w(const float* __restrict__ src, __nv_bfloat16* __restrict__ dst,
                       int rows, int src_ld, int col0, int cols)
{
    int half = cols >> 1;
    long tot = (long)rows*half;
    for (long i = (long)blockIdx.x*blockDim.x + threadIdx.x; i < tot; i += (long)gridDim.x*blockDim.x) {
        int r = (int)(i/half), c = (int)(i - (long)r*half)*2;
        float2 v = *(const float2*)&src[(size_t)r*src_ld + col0 + c];
        *(__nv_bfloat162*)&dst[(size_t)r*cols + c] = __floats2bfloat162_rn(v.x, v.y);
    }
}

// ---------------- grid barrier ----------------
__device__ __forceinline__ void grid_bar()
{
    __threadfence();
    __syncthreads();
    if (threadIdx.x == 0) {
        volatile unsigned* gen = &g_bar_gen;
        unsigned g = *gen;
        unsigned a = atomicAdd(&g_bar_cnt, 1u);
        if (a == GRID-1u) { g_bar_cnt = 0u; __threadfence(); atomicAdd(&g_bar_gen, 1u); }
        else while (*gen == g) __nanosleep(32);
    }
    __syncthreads();
    __threadfence();
}

// ---------------- persist building blocks ----------------
__device__ __forceinline__ void stage_bf16(const __nv_bfloat16* __restrict__ A, int K,
                                           __nv_bfloat16* __restrict__ sd)
{
    int Kc = K >> 3;
    for (int i = threadIdx.x; i < 32*Kc; i += TPB) {
        int row = i/Kc, c = i - row*Kc;
        *(uint4*)&sd[row*SLDA + (c<<3)] = *(const uint4*)&A[row*K + (c<<3)];
    }
}
__device__ __forceinline__ void gen_accum(const __nv_bfloat16* __restrict__ sAp,
    const __nv_bfloat16* __restrict__ Wp, int Kld, int nbase, int kb, int ke,
    float* acc, int lane)
{
    const __nv_bfloat16* ar = sAp + (lane&15)*SLDA + 8*(lane>>4);
    const __nv_bfloat16* w0 = Wp + (size_t)(nbase + (lane>>2))*Kld + 2*(lane&3);
    const __nv_bfloat16* w1 = w0 + (size_t)8*Kld;
    #pragma unroll 4
    for (int kk = kb; kk < ke; kk++) {
        int k0 = kk*16;
        unsigned a0[4], a1[4], b0[2], b1[2];
        ldsm4(a0, ar + k0);
        ldsm4(a1, ar + 16*SLDA + k0);
        b0[0] = *(const unsigned*)(w0 + k0); b0[1] = *(const unsigned*)(w0 + k0 + 8);
        b1[0] = *(const unsigned*)(w1 + k0); b1[1] = *(const unsigned*)(w1 + k0 + 8);
        mma16816(acc+0, a0, b0);  mma16816(acc+8, a1, b0);
        mma16816(acc+4, a0, b1);  mma16816(acc+12, a1, b1);
    }
}
__device__ __forceinline__ void red_store(float* red, int wrp, int lane, const float* acc)
{
    float* p = red + (wrp*32 + lane)*17;
    #pragma unroll
    for (int i = 0; i < 16; i++) p[i] = acc[i];
}
__device__ __forceinline__ float red_gather(const float* red, int ts, int li, int ai)
{
    const float* p = red + (ts*4*32 + li)*17 + ai;
    return p[0] + p[32*17] + p[2*32*17] + p[3*32*17];
}
__device__ __forceinline__ void elem_map(int b, int jl, int& li, int& ai)
{
    li = (b&7)*4 + ((jl&7)>>1);
    ai = (b>>4)*8 + (jl>>3)*4 + ((b>>3)&1)*2 + (jl&1);
}

// ---------------- persistent tensor-core sequential phase ----------------
__global__ __launch_bounds__(TPB, 1) void persist_kernel(
    const float* __restrict__ w2p_b, const float* __restrict__ p2w_b,
    const float* __restrict__ w_bih1, const float* __restrict__ w_bhh1,
    float* __restrict__ S)
{
    extern __shared__ char smem[];
    __nv_bfloat16* sA1 = (__nv_bfloat16*)(smem + SMEM_A1);
    __nv_bfloat16* sA2 = (__nv_bfloat16*)(smem + SMEM_A2);
    float* red = (float*)(smem + SMEM_RED);

    float* gpseq = S + OFF_GPSEQ;
    float* gwseq = S + OFF_GWSEQ;
    float* pc    = S + OFF_PC;
    float* wc0   = S + OFF_WC0;
    float* wc1   = S + OFF_WC1;
    float* wg0h  = S + OFF_WG0H;
    float* wg1h  = S + OFF_WG1H;
    float* phseq = S + OFF_PHSEQ;

    int lane = threadIdx.x & 31;
    int wrp  = threadIdx.x >> 5;
    int ts   = wrp >> 2;
    int ks   = wrp & 3;
    int eb   = threadIdx.x >> 4;   // epilogue batch (coalesced map)
    int ej   = threadIdx.x & 15;   // epilogue j-lane
    int eli, eai;
    elem_map(eb, ej, eli, eai);
    int pp = 0;

    for (int t = 0; t < TT; t++) {
        // ===== S1: lastw(tanh), wg1h, wg0h — 576 tiles / 144 blocks =====
        if (blockIdx.x < 144) {
            const __nv_bfloat16* sAu;
            if (blockIdx.x < 80) { stage_bf16(g_bwh1, 1024, sA1); sAu = sA1; }
            else                 { stage_bf16(g_bwh0, 1024, sA2); sAu = sA2; }
            __syncthreads();
            int tile = blockIdx.x*4 + ts;
            const __nv_bfloat16* Wp; int n0;
            if (tile < 64)       { Wp = g_bw2p;  n0 = tile*16; }
            else if (tile < 320) { Wp = g_bwhh1; n0 = (tile-64)*16; }
            else                 { Wp = g_bwhh0; n0 = (tile-320)*16; }
            float acc[16];
            #pragma unroll
            for (int i = 0; i < 16; i++) acc[i] = 0.f;
            gen_accum(sAu, Wp, 1024, n0, ks*16, ks*16+16, acc, lane);
            red_store(red, wrp, lane, acc);
            __syncthreads();
            #pragma unroll
            for (int tt2 = 0; tt2 < 4; tt2++) {
                int tl = blockIdx.x*4 + tt2;
                float v = red_gather(red, tt2, eli, eai);
                if (tl < 64) {
                    int n = tl*16 + ej;
                    g_blastw[eb*1024 + n] = __float2bfloat16(tanhf(v + w2p_b[n]));
                } else if (tl < 320) {
                    wg1h[eb*4096 + (tl-64)*16 + ej] = v;
                } else {
                    wg0h[eb*4096 + (tl-320)*16 + ej] = v;
                }
            }
        }
        grid_bar();

        // ===== S2: POS gates + cell — 16 blocks, K = 1024 + 256 =====
        if (blockIdx.x < 16) {
            stage_bf16(g_blastw, 1024, sA1);
            stage_bf16(g_bph[pp], 256, sA2);
            __syncthreads();
            int j0 = blockIdx.x*16;
            int nbase = ts*PH + j0;
            float acc[16];
            #pragma unroll
            for (int i = 0; i < 16; i++) acc[i] = 0.f;
            int sb = ks*20, se = sb + 20;
            if (sb < 64) gen_accum(sA1, g_bpih, 1024, nbase, sb, se < 64 ? se : 64, acc, lane);
            if (se > 64) gen_accum(sA2, g_bphh, 256, nbase, sb > 64 ? sb-64 : 0, se-64, acc, lane);
            red_store(red, wrp, lane, acc);
            __syncthreads();
            {
                int j = j0 + ej;
                const float* pre = gpseq + ((size_t)t*BATCH + eb)*(4*PH) + j;
                float gi = red_gather(red, 0, eli, eai) + pre[0*PH];
                float gf = red_gather(red, 1, eli, eai) + pre[1*PH];
                float gg = red_gather(red, 2, eli, eai) + pre[2*PH];
                float go = red_gather(red, 3, eli, eai) + pre[3*PH];
                int idx = eb*PH + j;
                float cn = sigf(gf)*pc[idx] + sigf(gi)*tanhf(gg);
                float hn = sigf(go)*tanhf(cn);
                pc[idx] = cn;
                g_bph[pp^1][idx] = __float2bfloat16(hn);
                phseq[((size_t)t*BATCH + eb)*PH + j] = hn;
            }
        }
        grid_bar();

        // ===== S4: lastp prologue + WORD L0 gates + cell — 64 blocks =====
        if (blockIdx.x < 64) {
            stage_bf16(g_bph[pp^1], 256, sA2);
            __syncthreads();
            {
                int n0 = wrp*16;
                float acc[16];
                #pragma unroll
                for (int i = 0; i < 16; i++) acc[i] = 0.f;
                gen_accum(sA2, g_bp2w, 256, n0, 0, 16, acc, lane);
                #pragma unroll
                for (int mf = 0; mf < 2; mf++)
                #pragma unroll
                for (int f = 0; f < 2; f++) {
                    int rb = mf*16 + (lane>>2);
                    int cl = n0 + f*8 + 2*(lane&3);
                    float b0 = p2w_b[cl], b1 = p2w_b[cl+1];
                    const float* a = acc + mf*8 + f*4;
                    *(__nv_bfloat162*)&sA1[rb*SLDA + cl] =
                        __floats2bfloat162_rn(tanhf(a[0]+b0), tanhf(a[1]+b1));
                    *(__nv_bfloat162*)&sA1[(rb+8)*SLDA + cl] =
                        __floats2bfloat162_rn(tanhf(a[2]+b0), tanhf(a[3]+b1));
                }
            }
            __syncthreads();
            int j0 = blockIdx.x*16;
            int nbase = ts*WH + j0;
            float acc[16];
            #pragma unroll
            for (int i = 0; i < 16; i++) acc[i] = 0.f;
            gen_accum(sA1, g_bwih0p, 256, nbase, ks*4, ks*4+4, acc, lane);
            red_store(red, wrp, lane, acc);
            __syncthreads();
            {
                int j = j0 + ej;
                const float* pre = gwseq + ((size_t)t*BATCH + eb)*(4*WH) + j;
                const float* hid = wg0h + (size_t)eb*4096 + j;
                float gi = red_gather(red, 0, eli, eai) + pre[0*WH] + hid[0*WH];
                float gf = red_gather(red, 1, eli, eai) + pre[1*WH] + hid[1*WH];
                float gg = red_gather(red, 2, eli, eai) + pre[2*WH] + hid[2*WH];
                float go = red_gather(red, 3, eli, eai) + pre[3*WH] + hid[3*WH];
                int idx = eb*WH + j;
                float cn = sigf(gf)*wc0[idx] + sigf(gi)*tanhf(gg);
                float hn = sigf(go)*tanhf(cn);
                wc0[idx] = cn;
                g_bwh0[idx] = __float2bfloat16(hn);
            }
        }
        grid_bar();

        // ===== S5: WORD L1 gates + cell — 64 blocks, K=1024 =====
        if (blockIdx.x < 64) {
            stage_bf16(g_bwh0, 1024, sA1);
            __syncthreads();
            int j0 = blockIdx.x*16;
            int nbase = ts*WH + j0;
            float acc[16];
            #pragma unroll
            for (int i = 0; i < 16; i++) acc[i] = 0.f;
            gen_accum(sA1, g_bwih1, 1024, nbase, ks*16, ks*16+16, acc, lane);
            red_store(red, wrp, lane, acc);
            __syncthreads();
            {
                int j = j0 + ej;
                const float* hid = wg1h + (size_t)eb*4096 + j;
                float gi = red_gather(red, 0, eli, eai) + hid[0*WH] + w_bih1[0*WH+j] + w_bhh1[0*WH+j];
                float gf = red_gather(red, 1, eli, eai) + hid[1*WH] + w_bih1[1*WH+j] + w_bhh1[1*WH+j];
                float gg = red_gather(red, 2, eli, eai) + hid[2*WH] + w_bih1[2*WH+j] + w_bhh1[2*WH+j];
                float go = red_gather(red, 3, eli, eai) + hid[3*WH] + w_bih1[3*WH+j] + w_bhh1[3*WH+j];
                int idx = eb*WH + j;
                float cn = sigf(gf)*wc1[idx] + sigf(gi)*tanhf(gg);
                float hn = sigf(go)*tanhf(cn);
                wc1[idx] = cn;
                g_bwh1[idx] = __float2bfloat16(hn);
                g_whseq_bf[((size_t)t*BATCH + eb)*WH + j] = __float2bfloat16(hn);
            }
        }
        grid_bar();
        pp ^= 1;
    }
}

// ---------------- generic bf16 mma GEMM: C[M,N] = A[M,K] @ B[N,K]^T + b1 (+b2) ----------------
template<int OUT_BF>
__global__ __launch_bounds__(256) void mma_gemm(const __nv_bfloat16* __restrict__ Abf,
                                                const __nv_bfloat16* __restrict__ Bbf,
                                                const float* __restrict__ bias1,
                                                const float* __restrict__ bias2,
                                                void* __restrict__ Cv, int N, int K)
{
    __shared__ __nv_bfloat16 sAm[128][40];
    __shared__ __nv_bfloat16 sBm[128][40];
    int tid = threadIdx.x, lane = tid&31, wid = tid>>5;
    int wm = wid>>2, wn = wid&3;
    int bm = blockIdx.y*128, bn = blockIdx.x*128;
    float acc[4][4][4] = {};
    for (int kt = 0; kt < K; kt += 32) {
        __syncthreads();
        #pragma unroll
        for (int c = 0; c < 2; c++) {
            int ch = tid + c*256;
            int row = ch>>2, seg = (ch&3)*8;
            *(uint4*)&sAm[row][seg] = *(const uint4*)&Abf[(size_t)(bm+row)*K + kt + seg];
            *(uint4*)&sBm[row][seg] = *(const uint4*)&Bbf[(size_t)(bn+row)*K + kt + seg];
        }
        __syncthreads();
        #pragma unroll
        for (int k16 = 0; k16 < 2; k16++) {
            unsigned afrag[4][4], bfrag[4][2];
            #pragma unroll
            for (int mf = 0; mf < 4; mf++)
                ldsm4(afrag[mf], &sAm[wm*64 + mf*16 + (lane&15)][k16*16 + (lane>>4)*8]);
            #pragma unroll
            for (int np = 0; np < 2; np++) {
                unsigned r[4];
                ldsm4(r, &sBm[wn*32 + np*16 + (lane&7) + ((lane>>4)<<3)][k16*16 + (((lane>>3)&1)<<3)]);
                bfrag[np*2][0] = r[0]; bfrag[np*2][1] = r[1];
                bfrag[np*2+1][0] = r[2]; bfrag[np*2+1][1] = r[3];
            }
            #pragma unroll
            for (int mf = 0; mf < 4; mf++)
                #pragma unroll
                for (int nf = 0; nf < 4; nf++)
                    mma16816(acc[mf][nf], afrag[mf], bfrag[nf]);
        }
    }
    int tg = lane>>2, tc = (lane&3)*2;
    #pragma unroll
    for (int nf = 0; nf < 4; nf++) {
        int n = bn + wn*32 + nf*8 + tc;
        float b0 = (bias1 ? bias1[n]   : 0.f) + (bias2 ? bias2[n]   : 0.f);
        float b1 = (bias1 ? bias1[n+1] : 0.f) + (bias2 ? bias2[n+1] : 0.f);
        #pragma unroll
        for (int mf = 0; mf < 4; mf++) {
            int m0 = bm + wm*64 + mf*16 + tg;
            float v00 = acc[mf][nf][0]+b0, v01 = acc[mf][nf][1]+b1;
            float v10 = acc[mf][nf][2]+b0, v11 = acc[mf][nf][3]+b1;
            if (OUT_BF) {
                __nv_bfloat16* C = (__nv_bfloat16*)Cv;
                *(__nv_bfloat162*)&C[(size_t)m0*N + n]     = __floats2bfloat162_rn(v00, v01);
                *(__nv_bfloat162*)&C[(size_t)(m0+8)*N + n] = __floats2bfloat162_rn(v10, v11);
            } else {
                float* C = (float*)Cv;
                *(float2*)&C[(size_t)m0*N + n]     = make_float2(v00, v01);
                *(float2*)&C[(size_t)(m0+8)*N + n] = make_float2(v10, v11);
            }
        }
    }
}

// ---------------- pos projection + log_softmax ----------------
__global__ void pos_out_kernel(const float* __restrict__ phseq, const float* __restrict__ proj_W,
                               const float* __restrict__ proj_b, float* __restrict__ out)
{
    int row = blockIdx.x;
    const float* h = phseq + row*PH;
    __shared__ float sh[PH];
    __shared__ float logits[PV];
    __shared__ float lse;
    for (int i = threadIdx.x; i < PH; i += 64) sh[i] = h[i];
    __syncthreads();
    if (threadIdx.x < PV) {
        float s = proj_b[threadIdx.x];
        const float* wr = proj_W + threadIdx.x*PH;
        #pragma unroll 4
        for (int k = 0; k < PH; k++) s += sh[k]*wr[k];
        logits[threadIdx.x] = s;
    }
    __syncthreads();
    if (threadIdx.x == 0) {
        float m = -1e30f;
        for (int i = 0; i < PV; i++) m = fmaxf(m, logits[i]);
        float ssum = 0.f;
        for (int i = 0; i < PV; i++) ssum += expf(logits[i]-m);
        lse = m + logf(ssum);
    }
    __syncthreads();
    if (threadIdx.x < PV) out[row*PV + threadIdx.x] = logits[threadIdx.x] - lse;
}

// ---------------- in-place log_softmax (word) ----------------
__global__ void word_lsm(float* __restrict__ out)
{
    int row = blockIdx.x;
    float* r = out + (long)row*WV;
    float m = -1e30f, s = 0.f;
    for (int i = threadIdx.x; i < WV; i += blockDim.x) {
        float v = r[i];
        if (v > m) { s = s*expf(m-v) + 1.f; m = v; } else s += expf(v-m);
    }
    __shared__ float sm[256], ss[256];
    sm[threadIdx.x] = m; ss[threadIdx.x] = s;
    __syncthreads();
    for (int off = 128; off > 0; off >>= 1) {
        if (threadIdx.x < off) {
            float m1 = sm[threadIdx.x], s1 = ss[threadIdx.x];
            float m2 = sm[threadIdx.x+off], s2 = ss[threadIdx.x+off];
            float mm = fmaxf(m1, m2);
            sm[threadIdx.x] = mm;
            ss[threadIdx.x] = s1*expf(m1-mm) + s2*expf(m2-mm);
        }
        __syncthreads();
    }
    float lse = sm[0] + logf(ss[0]);
    for (int i = threadIdx.x; i < WV; i += blockDim.x) r[i] -= lse;
}

// ---------------- host ----------------
extern "C" void kernel_launch(void* const* d_in, const int* in_sizes, int n_in,
                              void* d_out, int out_size)
{
    (void)in_sizes; (void)n_in; (void)out_size;
    const int*   pos          = (const int*)  d_in[0];
    const int*   word         = (const int*)  d_in[1];
    const float* pos_emb_W    = (const float*)d_in[2];
    const float* word_emb_W   = (const float*)d_in[3];
    const float* w2p_W        = (const float*)d_in[4];
    const float* w2p_b        = (const float*)d_in[5];
    const float* p2w_W        = (const float*)d_in[6];
    const float* p2w_b        = (const float*)d_in[7];
    const float* p_Wih0       = (const float*)d_in[8];
    const float* p_Whh0       = (const float*)d_in[9];
    const float* p_bih0       = (const float*)d_in[10];
    const float* p_bhh0       = (const float*)d_in[11];
    const float* w_Wih0       = (const float*)d_in[12];
    const float* w_Whh0       = (const float*)d_in[13];
    const float* w_bih0       = (const float*)d_in[14];
    const float* w_bhh0       = (const float*)d_in[15];
    const float* w_Wih1       = (const float*)d_in[16];
    const float* w_Whh1       = (const float*)d_in[17];
    const float* w_bih1       = (const float*)d_in[18];
    const float* w_bhh1       = (const float*)d_in[19];
    const float* pos_proj_W   = (const float*)d_in[20];
    const float* pos_proj_b   = (const float*)d_in[21];
    const float* word_proj1_W = (const float*)d_in[22];
    const float* word_proj1_b = (const float*)d_in[23];
    const float* word_proj2_b = (const float*)d_in[24];
    float* out = (float*)d_out;

    float* S; cudaGetSymbolAddress((void**)&S, g_scratch);
    __nv_bfloat16 *wemb_bf, *he_bf, *bw2p, *bwhh1, *bwhh0, *bpih, *bphh, *bp2w, *bwih0p, *bwih1;
    __nv_bfloat16 *bpihe, *bwih0e, *bproj1, *pembin, *wembin, *whseq_bf;
    cudaGetSymbolAddress((void**)&wemb_bf, g_wemb_bf);
    cudaGetSymbolAddress((void**)&he_bf, g_he_bf);
    cudaGetSymbolAddress((void**)&bw2p, g_bw2p);
    cudaGetSymbolAddress((void**)&bwhh1, g_bwhh1);
    cudaGetSymbolAddress((void**)&bwhh0, g_bwhh0);
    cudaGetSymbolAddress((void**)&bpih, g_bpih);
    cudaGetSymbolAddress((void**)&bphh, g_bphh);
    cudaGetSymbolAddress((void**)&bp2w, g_bp2w);
    cudaGetSymbolAddress((void**)&bwih0p, g_bwih0p);
    cudaGetSymbolAddress((void**)&bwih1, g_bwih1);
    cudaGetSymbolAddress((void**)&bpihe, g_bpihe);
    cudaGetSymbolAddress((void**)&bwih0e, g_bwih0e);
    cudaGetSymbolAddress((void**)&bproj1, g_bproj1);
    cudaGetSymbolAddress((void**)&pembin, g_pembin);
    cudaGetSymbolAddress((void**)&wembin, g_wembin);
    cudaGetSymbolAddress((void**)&whseq_bf, g_whseq_bf);

    float* gpseq = S + OFF_GPSEQ;
    float* gwseq = S + OFF_GWSEQ;
    float* phseq = S + OFF_PHSEQ;

    static bool attr_set = false;
    if (!attr_set) {
        cudaFuncSetAttribute(persist_kernel, cudaFuncAttributeMaxDynamicSharedMemorySize, SMEM_DYN);
        attr_set = true;
    }

    init_kernel<<<512, 256>>>(pos, word, pos_emb_W, word_emb_W, S);
    conv_bf16<<<2048, 256>>>(word_emb_W, wemb_bf, (int)((size_t)WV*WE/4));

    conv_w<<<512, 256>>>(w2p_W,        bw2p,   1024, 1024, 0,   1024);
    conv_w<<<512, 256>>>(w_Whh1,       bwhh1,  4096, 1024, 0,   1024);
    conv_w<<<512, 256>>>(w_Whh0,       bwhh0,  4096, 1024, 0,   1024);
    conv_w<<<512, 256>>>(p_Wih0,       bpih,   1024, 1152, 128, 1024);
    conv_w<<<512, 256>>>(p_Whh0,       bphh,   1024, 256,  0,   256);
    conv_w<<<512, 256>>>(p2w_W,        bp2w,   256,  256,  0,   256);
    conv_w<<<512, 256>>>(w_Wih0,       bwih0p, 4096, 768,  512, 256);
    conv_w<<<512, 256>>>(w_Wih1,       bwih1,  4096, 1024, 0,   1024);
    conv_w<<<512, 256>>>(p_Wih0,       bpihe,  1024, 1152, 0,   128);
    conv_w<<<512, 256>>>(w_Wih0,       bwih0e, 4096, 768,  0,   512);
    conv_w<<<512, 256>>>(word_proj1_W, bproj1, 512,  1024, 0,   1024);

    // input-side gate precomputes (tensor cores)
    mma_gemm<0><<<dim3(4*PH/128, TT*BATCH/128), 256>>>(pembin, bpihe, p_bih0, p_bhh0,
                                                       gpseq, 4*PH, PE);
    mma_gemm<0><<<dim3(4*WH/128, TT*BATCH/128), 256>>>(wembin, bwih0e, w_bih0, w_bhh0,
                                                       gwseq, 4*WH, WE);

    persist_kernel<<<GRID, TPB, SMEM_DYN>>>(w2p_b, p2w_b, w_bih1, w_bhh1, S);

    pos_out_kernel<<<TT*BATCH, 64>>>(phseq, pos_proj_W, pos_proj_b, out);

    // he = whseq @ proj1^T + b (bf16 out), then vocab logits
    mma_gemm<1><<<dim3(WE/128, TT*BATCH/128), 256>>>(whseq_bf, bproj1, word_proj1_b, nullptr,
                                                     he_bf, WE, WH);
    float* wout = out + (long)TT*BATCH*PV;
    mma_gemm<0><<<dim3(WV/128, TT*BATCH/128), 256>>>(he_bf, wemb_bf, word_proj2_b, nullptr,
                                                     wout, WV, WE);
    word_lsm<<<TT*BATCH, 256>>>(wout);
}

// round 10
// speedup vs baseline: 2.4373x; 1.0048x over previous
#include <cuda_runtime.h>
#include <cuda_bf16.h>
#include <math.h>

#define TT 64
#define BATCH 32
#define PE 128
#define WE 512
#define PH 256
#define WH 1024
#define PV 48
#define WV 32000
#define GRID 148
#define TPB 512
#define SLDA 1032

// ---------------- fp32 scratch ----------------
#define OFF_GPSEQ 0
#define OFF_GWSEQ (OFF_GPSEQ + TT*BATCH*4*PH)
#define OFF_PC    (OFF_GWSEQ + TT*BATCH*4*WH)
#define OFF_WC0   (OFF_PC + BATCH*PH)
#define OFF_WC1   (OFF_WC0 + BATCH*WH)
#define OFF_WG0H  (OFF_WC1 + BATCH*WH)
#define OFF_WG1H  (OFF_WG0H + BATCH*4*WH)
#define OFF_PHSEQ (OFF_WG1H + BATCH*4*WH)
#define SCRATCH_TOTAL (OFF_PHSEQ + TT*BATCH*PH)

__device__ float g_scratch[SCRATCH_TOTAL];
__device__ volatile unsigned g_flags[GRID];
__device__ volatile unsigned g_gen;

// bf16 weights (compact [N,K]) + states + activations
__device__ __nv_bfloat16 g_bw2p  [1024*1024];
__device__ __nv_bfloat16 g_bwhh1 [4096*1024];
__device__ __nv_bfloat16 g_bwhh0 [4096*1024];
__device__ __nv_bfloat16 g_bpih  [1024*1024];
__device__ __nv_bfloat16 g_bphh  [1024*256];
__device__ __nv_bfloat16 g_bp2w  [256*256];
__device__ __nv_bfloat16 g_bwih0p[4096*256];
__device__ __nv_bfloat16 g_bwih1 [4096*1024];
__device__ __nv_bfloat16 g_bpihe [1024*128];
__device__ __nv_bfloat16 g_bwih0e[4096*512];
__device__ __nv_bfloat16 g_bproj1[512*1024];
__device__ __nv_bfloat16 g_bwh1  [32*1024];
__device__ __nv_bfloat16 g_bwh0  [32*1024];
__device__ __nv_bfloat16 g_bph   [2][32*256];
__device__ __nv_bfloat16 g_blastw[32*1024];
__device__ __nv_bfloat16 g_pembin[TT*BATCH*PE];
__device__ __nv_bfloat16 g_wembin[TT*BATCH*WE];
__device__ __nv_bfloat16 g_whseq_bf[(size_t)TT*BATCH*WH];
__device__ __nv_bfloat16 g_wemb_bf[(size_t)WV*WE];
__device__ __nv_bfloat16 g_he_bf[(size_t)TT*BATCH*WE];

#define SMEM_A1  0
#define SMEM_A2  66048
#define SMEM_RED 132096
#define SMEM_DYN 166912

__device__ __forceinline__ float sigf(float x) { return 1.f/(1.f+expf(-x)); }

__device__ __forceinline__ void mma16816(float* c, const unsigned* a, const unsigned* b)
{
    asm volatile("mma.sync.aligned.m16n8k16.row.col.f32.bf16.bf16.f32 "
        "{%0,%1,%2,%3}, {%4,%5,%6,%7}, {%8,%9}, {%0,%1,%2,%3};"
        : "+f"(c[0]), "+f"(c[1]), "+f"(c[2]), "+f"(c[3])
        : "r"(a[0]), "r"(a[1]), "r"(a[2]), "r"(a[3]), "r"(b[0]), "r"(b[1]));
}
__device__ __forceinline__ void ldsm4(unsigned* r, const void* p)
{
    unsigned ad = (unsigned)__cvta_generic_to_shared(p);
    asm volatile("ldmatrix.sync.aligned.m8n8.x4.shared.b16 {%0,%1,%2,%3}, [%4];"
        : "=r"(r[0]), "=r"(r[1]), "=r"(r[2]), "=r"(r[3]) : "r"(ad));
}

// ---------------- init ----------------
__global__ void init_kernel(const int* __restrict__ pos, const int* __restrict__ word,
                            const float* __restrict__ pos_emb, const float* __restrict__ word_emb,
                            float* __restrict__ S)
{
    int i = blockIdx.x*blockDim.x + threadIdx.x;
    int st = gridDim.x*blockDim.x;
    for (int x = i; x < TT*BATCH*PE; x += st) {
        int tb = x/PE;
        g_pembin[x] = __float2bfloat16(pos_emb[pos[tb]*PE + x - tb*PE]);
    }
    for (int x = i; x < TT*BATCH*WE; x += st) {
        int tb = x/WE;
        g_wembin[x] = __float2bfloat16(word_emb[word[tb]*WE + x - tb*WE]);
    }
    for (int x = i; x < BATCH*PH; x += st) S[OFF_PC + x] = 0.f;
    for (int x = i; x < 2*BATCH*WH; x += st) S[OFF_WC0 + x] = 0.f;
    unsigned* z1 = (unsigned*)g_bwh1; unsigned* z2 = (unsigned*)g_bwh0; unsigned* z3 = (unsigned*)g_bph;
    for (int x = i; x < 16384; x += st) { z1[x] = 0u; z2[x] = 0u; }
    for (int x = i; x < 8192; x += st) z3[x] = 0u;
    if (i < GRID) g_flags[i] = 0u;
    if (i == 0) g_gen = 0u;
}

// ---------------- conversions ----------------
__global__ void conv_bf16(const float* __restrict__ src, __nv_bfloat16* __restrict__ dst, int n4)
{
    int i = blockIdx.x*blockDim.x + threadIdx.x;
    int st = gridDim.x*blockDim.x;
    const float4* s4 = (const float4*)src;
    for (; i < n4; i += st) {
        float4 v = s4[i];
        *(__nv_bfloat162*)(dst + (size_t)i*4)   = __floats2bfloat162_rn(v.x, v.y);
        *(__nv_bfloat162*)(dst + (size_t)i*4+2) = __floats2bfloat162_rn(v.z, v.w);
    }
}
__device__ __forceinline__ void conv_seg(const float* __restrict__ src, __nv_bfloat16* __restrict__ dst,
                                         int rows, int src_ld, int col0, int cols)
{
    int half = cols >> 1;
    long tot = (long)rows*half;
    long idx = (long)blockIdx.x*blockDim.x + threadIdx.x;
    long st  = (long)gridDim.x*blockDim.x;
    for (long i = idx; i < tot; i += st) {
        int r = (int)(i/half), c = (int)(i - (long)r*half)*2;
        float2 v = *(const float2*)&src[(size_t)r*src_ld + col0 + c];
        *(__nv_bfloat162*)&dst[(size_t)r*cols + c] = __floats2bfloat162_rn(v.x, v.y);
    }
}
__global__ void conv_all(const float* w2p_W, const float* w_Whh1, const float* w_Whh0,
                         const float* p_Wih0, const float* p_Whh0, const float* p2w_W,
                         const float* w_Wih0, const float* w_Wih1, const float* word_proj1_W)
{
    conv_seg(w2p_W,        g_bw2p,   1024, 1024, 0,   1024);
    conv_seg(w_Whh1,       g_bwhh1,  4096, 1024, 0,   1024);
    conv_seg(w_Whh0,       g_bwhh0,  4096, 1024, 0,   1024);
    conv_seg(p_Wih0,       g_bpih,   1024, 1152, 128, 1024);
    conv_seg(p_Whh0,       g_bphh,   1024, 256,  0,   256);
    conv_seg(p2w_W,        g_bp2w,   256,  256,  0,   256);
    conv_seg(w_Wih0,       g_bwih0p, 4096, 768,  512, 256);
    conv_seg(w_Wih1,       g_bwih1,  4096, 1024, 0,   1024);
    conv_seg(p_Wih0,       g_bpihe,  1024, 1152, 0,   128);
    conv_seg(w_Wih0,       g_bwih0e, 4096, 768,  0,   512);
    conv_seg(word_proj1_W, g_bproj1, 512,  1024, 0,   1024);
}

// ---------------- flag-based grid barrier (no atomic contention) ----------------
__device__ __forceinline__ void grid_bar(unsigned epoch)
{
    __threadfence();
    __syncthreads();
    if (threadIdx.x == 0) g_flags[blockIdx.x] = epoch;
    if (blockIdx.x == 0) {
        if (threadIdx.x < GRID)
            while (g_flags[threadIdx.x] < epoch) { }
        __syncthreads();
        if (threadIdx.x == 0) { __threadfence(); g_gen = epoch; }
    }
    if (threadIdx.x == 0)
        while (g_gen < epoch) { }
    __syncthreads();
    __threadfence();
}

// ---------------- persist building blocks ----------------
__device__ __forceinline__ void stage_bf16(const __nv_bfloat16* __restrict__ A, int K,
                                           __nv_bfloat16* __restrict__ sd)
{
    int Kc = K >> 3;
    for (int i = threadIdx.x; i < 32*Kc; i += TPB) {
        int row = i/Kc, c = i - row*Kc;
        *(uint4*)&sd[row*SLDA + (c<<3)] = *(const uint4*)&A[row*K + (c<<3)];
    }
}
__device__ __forceinline__ void gen_accum(const __nv_bfloat16* __restrict__ sAp,
    const __nv_bfloat16* __restrict__ Wp, int Kld, int nbase, int kb, int ke,
    float* acc, int lane)
{
    const __nv_bfloat16* ar = sAp + (lane&15)*SLDA + 8*(lane>>4);
    const __nv_bfloat16* w0 = Wp + (size_t)(nbase + (lane>>2))*Kld + 2*(lane&3);
    const __nv_bfloat16* w1 = w0 + (size_t)8*Kld;
    #pragma unroll 4
    for (int kk = kb; kk < ke; kk++) {
        int k0 = kk*16;
        unsigned a0[4], a1[4], b0[2], b1[2];
        ldsm4(a0, ar + k0);
        ldsm4(a1, ar + 16*SLDA + k0);
        b0[0] = *(const unsigned*)(w0 + k0); b0[1] = *(const unsigned*)(w0 + k0 + 8);
        b1[0] = *(const unsigned*)(w1 + k0); b1[1] = *(const unsigned*)(w1 + k0 + 8);
        mma16816(acc+0, a0, b0);  mma16816(acc+8, a1, b0);
        mma16816(acc+4, a0, b1);  mma16816(acc+12, a1, b1);
    }
}
__device__ __forceinline__ void red_store(float* red, int wrp, int lane, const float* acc)
{
    float* p = red + (wrp*32 + lane)*17;
    #pragma unroll
    for (int i = 0; i < 16; i++) p[i] = acc[i];
}
__device__ __forceinline__ float red_gather(const float* red, int ts, int li, int ai)
{
    const float* p = red + (ts*4*32 + li)*17 + ai;
    return p[0] + p[32*17] + p[2*32*17] + p[3*32*17];
}
__device__ __forceinline__ void elem_map(int b, int jl, int& li, int& ai)
{
    li = (b&7)*4 + ((jl&7)>>1);
    ai = (b>>4)*8 + (jl>>3)*4 + ((b>>3)&1)*2 + (jl&1);
}

// ---------------- persistent tensor-core sequential phase ----------------
__global__ __launch_bounds__(TPB, 1) void persist_kernel(
    const float* __restrict__ w2p_b, const float* __restrict__ p2w_b,
    const float* __restrict__ w_bih1, const float* __restrict__ w_bhh1,
    float* __restrict__ S)
{
    extern __shared__ char smem[];
    __nv_bfloat16* sA1 = (__nv_bfloat16*)(smem + SMEM_A1);
    __nv_bfloat16* sA2 = (__nv_bfloat16*)(smem + SMEM_A2);
    float* red = (float*)(smem + SMEM_RED);

    float* gpseq = S + OFF_GPSEQ;
    float* gwseq = S + OFF_GWSEQ;
    float* pc    = S + OFF_PC;
    float* wc0   = S + OFF_WC0;
    float* wc1   = S + OFF_WC1;
    float* wg0h  = S + OFF_WG0H;
    float* wg1h  = S + OFF_WG1H;
    float* phseq = S + OFF_PHSEQ;

    int lane = threadIdx.x & 31;
    int wrp  = threadIdx.x >> 5;
    int ts   = wrp >> 2;
    int ks   = wrp & 3;
    int eb   = threadIdx.x >> 4;
    int ej   = threadIdx.x & 15;
    int eli, eai;
    elem_map(eb, ej, eli, eai);
    int pp = 0;
    unsigned epoch = 0;

    for (int t = 0; t < TT; t++) {
        // ===== A: lastw = tanh(wh1 @ w2p^T + b) — 64 tiles / 16 blocks =====
        if (blockIdx.x < 16) {
            stage_bf16(g_bwh1, 1024, sA1);
            __syncthreads();
            int tile = blockIdx.x*4 + ts;
            float acc[16];
            #pragma unroll
            for (int i = 0; i < 16; i++) acc[i] = 0.f;
            gen_accum(sA1, g_bw2p, 1024, tile*16, ks*16, ks*16+16, acc, lane);
            red_store(red, wrp, lane, acc);
            __syncthreads();
            #pragma unroll
            for (int tt2 = 0; tt2 < 4; tt2++) {
                int n = (blockIdx.x*4 + tt2)*16 + ej;
                float v = red_gather(red, tt2, eli, eai);
                g_blastw[eb*1024 + n] = __float2bfloat16(tanhf(v + w2p_b[n]));
            }
        }
        grid_bar(++epoch);

        // ===== B: POS gates+cell (blocks 0-15)  ||  wg1h/wg0h (blocks 16-147) =====
        if (blockIdx.x < 16) {
            stage_bf16(g_blastw, 1024, sA1);
            stage_bf16(g_bph[pp], 256, sA2);
            __syncthreads();
            int j0 = blockIdx.x*16;
            int nbase = ts*PH + j0;
            float acc[16];
            #pragma unroll
            for (int i = 0; i < 16; i++) acc[i] = 0.f;
            int sb = ks*20, se = sb + 20;
            if (sb < 64) gen_accum(sA1, g_bpih, 1024, nbase, sb, se < 64 ? se : 64, acc, lane);
            if (se > 64) gen_accum(sA2, g_bphh, 256, nbase, sb > 64 ? sb-64 : 0, se-64, acc, lane);
            red_store(red, wrp, lane, acc);
            __syncthreads();
            {
                int j = j0 + ej;
                const float* pre = gpseq + ((size_t)t*BATCH + eb)*(4*PH) + j;
                float gi = red_gather(red, 0, eli, eai) + pre[0*PH];
                float gf = red_gather(red, 1, eli, eai) + pre[1*PH];
                float gg = red_gather(red, 2, eli, eai) + pre[2*PH];
                float go = red_gather(red, 3, eli, eai) + pre[3*PH];
                int idx = eb*PH + j;
                float cn = sigf(gf)*pc[idx] + sigf(gi)*tanhf(gg);
                float hn = sigf(go)*tanhf(cn);
                pc[idx] = cn;
                g_bph[pp^1][idx] = __float2bfloat16(hn);
                phseq[((size_t)t*BATCH + eb)*PH + j] = hn;
            }
        } else {
            int base = (blockIdx.x - 16)*4;
            if (base < 512) {
                const __nv_bfloat16* sAu;
                if (base < 256) { stage_bf16(g_bwh1, 1024, sA1); sAu = sA1; }
                else            { stage_bf16(g_bwh0, 1024, sA2); sAu = sA2; }
                __syncthreads();
                int wt = base + ts;
                const __nv_bfloat16* Wp = (wt < 256) ? g_bwhh1 : g_bwhh0;
                int n0 = (wt < 256 ? wt : wt-256)*16;
                float acc[16];
                #pragma unroll
                for (int i = 0; i < 16; i++) acc[i] = 0.f;
                gen_accum(sAu, Wp, 1024, n0, ks*16, ks*16+16, acc, lane);
                red_store(red, wrp, lane, acc);
                __syncthreads();
                #pragma unroll
                for (int tt2 = 0; tt2 < 4; tt2++) {
                    int wt2 = base + tt2;
                    float v = red_gather(red, tt2, eli, eai);
                    if (wt2 < 256) wg1h[eb*4096 + wt2*16 + ej] = v;
                    else           wg0h[eb*4096 + (wt2-256)*16 + ej] = v;
                }
            }
        }
        grid_bar(++epoch);

        // ===== S4: lastp prologue + WORD L0 gates + cell — 64 blocks =====
        if (blockIdx.x < 64) {
            stage_bf16(g_bph[pp^1], 256, sA2);
            __syncthreads();
            {
                int n0 = wrp*16;
                float acc[16];
                #pragma unroll
                for (int i = 0; i < 16; i++) acc[i] = 0.f;
                gen_accum(sA2, g_bp2w, 256, n0, 0, 16, acc, lane);
                #pragma unroll
                for (int mf = 0; mf < 2; mf++)
                #pragma unroll
                for (int f = 0; f < 2; f++) {
                    int rb = mf*16 + (lane>>2);
                    int cl = n0 + f*8 + 2*(lane&3);
                    float b0 = p2w_b[cl], b1 = p2w_b[cl+1];
                    const float* a = acc + mf*8 + f*4;
                    *(__nv_bfloat162*)&sA1[rb*SLDA + cl] =
                        __floats2bfloat162_rn(tanhf(a[0]+b0), tanhf(a[1]+b1));
                    *(__nv_bfloat162*)&sA1[(rb+8)*SLDA + cl] =
                        __floats2bfloat162_rn(tanhf(a[2]+b0), tanhf(a[3]+b1));
                }
            }
            __syncthreads();
            int j0 = blockIdx.x*16;
            int nbase = ts*WH + j0;
            float acc[16];
            #pragma unroll
            for (int i = 0; i < 16; i++) acc[i] = 0.f;
            gen_accum(sA1, g_bwih0p, 256, nbase, ks*4, ks*4+4, acc, lane);
            red_store(red, wrp, lane, acc);
            __syncthreads();
            {
                int j = j0 + ej;
                const float* pre = gwseq + ((size_t)t*BATCH + eb)*(4*WH) + j;
                const float* hid = wg0h + (size_t)eb*4096 + j;
                float gi = red_gather(red, 0, eli, eai) + pre[0*WH] + hid[0*WH];
                float gf = red_gather(red, 1, eli, eai) + pre[1*WH] + hid[1*WH];
                float gg = red_gather(red, 2, eli, eai) + pre[2*WH] + hid[2*WH];
                float go = red_gather(red, 3, eli, eai) + pre[3*WH] + hid[3*WH];
                int idx = eb*WH + j;
                float cn = sigf(gf)*wc0[idx] + sigf(gi)*tanhf(gg);
                float hn = sigf(go)*tanhf(cn);
                wc0[idx] = cn;
                g_bwh0[idx] = __float2bfloat16(hn);
            }
        }
        grid_bar(++epoch);

        // ===== S5: WORD L1 gates + cell — 64 blocks, K=1024 =====
        if (blockIdx.x < 64) {
            stage_bf16(g_bwh0, 1024, sA1);
            __syncthreads();
            int j0 = blockIdx.x*16;
            int nbase = ts*WH + j0;
            float acc[16];
            #pragma unroll
            for (int i = 0; i < 16; i++) acc[i] = 0.f;
            gen_accum(sA1, g_bwih1, 1024, nbase, ks*16, ks*16+16, acc, lane);
            red_store(red, wrp, lane, acc);
            __syncthreads();
            {
                int j = j0 + ej;
                const float* hid = wg1h + (size_t)eb*4096 + j;
                float gi = red_gather(red, 0, eli, eai) + hid[0*WH] + w_bih1[0*WH+j] + w_bhh1[0*WH+j];
                float gf = red_gather(red, 1, eli, eai) + hid[1*WH] + w_bih1[1*WH+j] + w_bhh1[1*WH+j];
                float gg = red_gather(red, 2, eli, eai) + hid[2*WH] + w_bih1[2*WH+j] + w_bhh1[2*WH+j];
                float go = red_gather(red, 3, eli, eai) + hid[3*WH] + w_bih1[3*WH+j] + w_bhh1[3*WH+j];
                int idx = eb*WH + j;
                float cn = sigf(gf)*wc1[idx] + sigf(gi)*tanhf(gg);
                float hn = sigf(go)*tanhf(cn);
                wc1[idx] = cn;
                g_bwh1[idx] = __float2bfloat16(hn);
                g_whseq_bf[((size_t)t*BATCH + eb)*WH + j] = __float2bfloat16(hn);
            }
        }
        grid_bar(++epoch);
        pp ^= 1;
    }
}

// ---------------- generic bf16 mma GEMM ----------------
template<int OUT_BF>
__global__ __launch_bounds__(256) void mma_gemm(const __nv_bfloat16* __restrict__ Abf,
                                                const __nv_bfloat16* __restrict__ Bbf,
                                                const float* __restrict__ bias1,
                                                const float* __restrict__ bias2,
                                                void* __restrict__ Cv, int N, int K)
{
    __shared__ __nv_bfloat16 sAm[128][40];
    __shared__ __nv_bfloat16 sBm[128][40];
    int tid = threadIdx.x, lane = tid&31, wid = tid>>5;
    int wm = wid>>2, wn = wid&3;
    int bm = blockIdx.y*128, bn = blockIdx.x*128;
    float acc[4][4][4] = {};
    for (int kt = 0; kt < K; kt += 32) {
        __syncthreads();
        #pragma unroll
        for (int c = 0; c < 2; c++) {
            int ch = tid + c*256;
            int row = ch>>2, seg = (ch&3)*8;
            *(uint4*)&sAm[row][seg] = *(const uint4*)&Abf[(size_t)(bm+row)*K + kt + seg];
            *(uint4*)&sBm[row][seg] = *(const uint4*)&Bbf[(size_t)(bn+row)*K + kt + seg];
        }
        __syncthreads();
        #pragma unroll
        for (int k16 = 0; k16 < 2; k16++) {
            unsigned afrag[4][4], bfrag[4][2];
            #pragma unroll
            for (int mf = 0; mf < 4; mf++)
                ldsm4(afrag[mf], &sAm[wm*64 + mf*16 + (lane&15)][k16*16 + (lane>>4)*8]);
            #pragma unroll
            for (int np = 0; np < 2; np++) {
                unsigned r[4];
                ldsm4(r, &sBm[wn*32 + np*16 + (lane&7) + ((lane>>4)<<3)][k16*16 + (((lane>>3)&1)<<3)]);
                bfrag[np*2][0] = r[0]; bfrag[np*2][1] = r[1];
                bfrag[np*2+1][0] = r[2]; bfrag[np*2+1][1] = r[3];
            }
            #pragma unroll
            for (int mf = 0; mf < 4; mf++)
                #pragma unroll
                for (int nf = 0; nf < 4; nf++)
                    mma16816(acc[mf][nf], afrag[mf], bfrag[nf]);
        }
    }
    int tg = lane>>2, tc = (lane&3)*2;
    #pragma unroll
    for (int nf = 0; nf < 4; nf++) {
        int n = bn + wn*32 + nf*8 + tc;
        float b0 = (bias1 ? bias1[n]   : 0.f) + (bias2 ? bias2[n]   : 0.f);
        float b1 = (bias1 ? bias1[n+1] : 0.f) + (bias2 ? bias2[n+1] : 0.f);
        #pragma unroll
        for (int mf = 0; mf < 4; mf++) {
            int m0 = bm + wm*64 + mf*16 + tg;
            float v00 = acc[mf][nf][0]+b0, v01 = acc[mf][nf][1]+b1;
            float v10 = acc[mf][nf][2]+b0, v11 = acc[mf][nf][3]+b1;
            if (OUT_BF) {
                __nv_bfloat16* C = (__nv_bfloat16*)Cv;
                *(__nv_bfloat162*)&C[(size_t)m0*N + n]     = __floats2bfloat162_rn(v00, v01);
                *(__nv_bfloat162*)&C[(size_t)(m0+8)*N + n] = __floats2bfloat162_rn(v10, v11);
            } else {
                float* C = (float*)Cv;
                *(float2*)&C[(size_t)m0*N + n]     = make_float2(v00, v01);
                *(float2*)&C[(size_t)(m0+8)*N + n] = make_float2(v10, v11);
            }
        }
    }
}

// ---------------- pos projection + log_softmax ----------------
__global__ void pos_out_kernel(const float* __restrict__ phseq, const float* __restrict__ proj_W,
                               const float* __restrict__ proj_b, float* __restrict__ out)
{
    int row = blockIdx.x;
    const float* h = phseq + row*PH;
    __shared__ float sh[PH];
    __shared__ float logits[PV];
    __shared__ float lse;
    for (int i = threadIdx.x; i < PH; i += 64) sh[i] = h[i];
    __syncthreads();
    if (threadIdx.x < PV) {
        float s = proj_b[threadIdx.x];
        const float* wr = proj_W + threadIdx.x*PH;
        #pragma unroll 4
        for (int k = 0; k < PH; k++) s += sh[k]*wr[k];
        logits[threadIdx.x] = s;
    }
    __syncthreads();
    if (threadIdx.x == 0) {
        float m = -1e30f;
        for (int i = 0; i < PV; i++) m = fmaxf(m, logits[i]);
        float ssum = 0.f;
        for (int i = 0; i < PV; i++) ssum += expf(logits[i]-m);
        lse = m + logf(ssum);
    }
    __syncthreads();
    if (threadIdx.x < PV) out[row*PV + threadIdx.x] = logits[threadIdx.x] - lse;
}

// ---------------- in-place log_softmax (word) ----------------
__global__ void word_lsm(float* __restrict__ out)
{
    int row = blockIdx.x;
    float* r = out + (long)row*WV;
    float m = -1e30f, s = 0.f;
    for (int i = threadIdx.x; i < WV; i += blockDim.x) {
        float v = r[i];
        if (v > m) { s = s*expf(m-v) + 1.f; m = v; } else s += expf(v-m);
    }
    __shared__ float sm[256], ss[256];
    sm[threadIdx.x] = m; ss[threadIdx.x] = s;
    __syncthreads();
    for (int off = 128; off > 0; off >>= 1) {
        if (threadIdx.x < off) {
            float m1 = sm[threadIdx.x], s1 = ss[threadIdx.x];
            float m2 = sm[threadIdx.x+off], s2 = ss[threadIdx.x+off];
            float mm = fmaxf(m1, m2);
            sm[threadIdx.x] = mm;
            ss[threadIdx.x] = s1*expf(m1-mm) + s2*expf(m2-mm);
        }
        __syncthreads();
    }
    float lse = sm[0] + logf(ss[0]);
    for (int i = threadIdx.x; i < WV; i += blockDim.x) r[i] -= lse;
}

// ---------------- host ----------------
extern "C" void kernel_launch(void* const* d_in, const int* in_sizes, int n_in,
                              void* d_out, int out_size)
{
    (void)in_sizes; (void)n_in; (void)out_size;
    const int*   pos          = (const int*)  d_in[0];
    const int*   word         = (const int*)  d_in[1];
    const float* pos_emb_W    = (const float*)d_in[2];
    const float* word_emb_W   = (const float*)d_in[3];
    const float* w2p_W        = (const float*)d_in[4];
    const float* w2p_b        = (const float*)d_in[5];
    const float* p2w_W        = (const float*)d_in[6];
    const float* p2w_b        = (const float*)d_in[7];
    const float* p_Wih0       = (const float*)d_in[8];
    const float* p_Whh0       = (const float*)d_in[9];
    const float* p_bih0       = (const float*)d_in[10];
    const float* p_bhh0       = (const float*)d_in[11];
    const float* w_Wih0       = (const float*)d_in[12];
    const float* w_Whh0       = (const float*)d_in[13];
    const float* w_bih0       = (const float*)d_in[14];
    const float* w_bhh0       = (const float*)d_in[15];
    const float* w_Wih1       = (const float*)d_in[16];
    const float* w_Whh1       = (const float*)d_in[17];
    const float* w_bih1       = (const float*)d_in[18];
    const float* w_bhh1       = (const float*)d_in[19];
    const float* pos_proj_W   = (const float*)d_in[20];
    const float* pos_proj_b   = (const float*)d_in[21];
    const float* word_proj1_W = (const float*)d_in[22];
    const float* word_proj1_b = (const float*)d_in[23];
    const float* word_proj2_b = (const float*)d_in[24];
    float* out = (float*)d_out;

    float* S; cudaGetSymbolAddress((void**)&S, g_scratch);
    __nv_bfloat16 *wemb_bf, *he_bf, *pembin, *wembin, *whseq_bf, *bpihe, *bwih0e, *bproj1;
    cudaGetSymbolAddress((void**)&wemb_bf, g_wemb_bf);
    cudaGetSymbolAddress((void**)&he_bf, g_he_bf);
    cudaGetSymbolAddress((void**)&pembin, g_pembin);
    cudaGetSymbolAddress((void**)&wembin, g_wembin);
    cudaGetSymbolAddress((void**)&whseq_bf, g_whseq_bf);
    cudaGetSymbolAddress((void**)&bpihe, g_bpihe);
    cudaGetSymbolAddress((void**)&bwih0e, g_bwih0e);
    cudaGetSymbolAddress((void**)&bproj1, g_bproj1);

    float* gpseq = S + OFF_GPSEQ;
    float* gwseq = S + OFF_GWSEQ;
    float* phseq = S + OFF_PHSEQ;

    static bool attr_set = false;
    if (!attr_set) {
        cudaFuncSetAttribute(persist_kernel, cudaFuncAttributeMaxDynamicSharedMemorySize, SMEM_DYN);
        attr_set = true;
    }

    init_kernel<<<512, 256>>>(pos, word, pos_emb_W, word_emb_W, S);
    conv_bf16<<<2048, 256>>>(word_emb_W, wemb_bf, (int)((size_t)WV*WE/4));
    conv_all<<<592, 256>>>(w2p_W, w_Whh1, w_Whh0, p_Wih0, p_Whh0, p2w_W,
                           w_Wih0, w_Wih1, word_proj1_W);

    mma_gemm<0><<<dim3(4*PH/128, TT*BATCH/128), 256>>>(pembin, bpihe, p_bih0, p_bhh0,
                                                       gpseq, 4*PH, PE);
    mma_gemm<0><<<dim3(4*WH/128, TT*BATCH/128), 256>>>(wembin, bwih0e, w_bih0, w_bhh0,
                                                       gwseq, 4*WH, WE);

    persist_kernel<<<GRID, TPB, SMEM_DYN>>>(w2p_b, p2w_b, w_bih1, w_bhh1, S);

    pos_out_kernel<<<TT*BATCH, 64>>>(phseq, pos_proj_W, pos_proj_b, out);

    mma_gemm<1><<<dim3(WE/128, TT*BATCH/128), 256>>>(whseq_bf, bproj1, word_proj1_b, nullptr,
                                                     he_bf, WE, WH);
    float* wout = out + (long)TT*BATCH*PV;
    mma_gemm<0><<<dim3(WV/128, TT*BATCH/128), 256>>>(he_bf, wemb_bf, word_proj2_b, nullptr,
                                                     wout, WV, WE);
    word_lsm<<<TT*BATCH, 256>>>(wout);
}